// round 12
// baseline (speedup 1.0000x reference)
#include <cuda_runtime.h>
#include <cuda_bf16.h>
#include <cstdint>

#define NNODES   50000
#define ETOT_MAX 900000
#define HID      256
#define NHEAD    8
#define SCAN_NB  196          // 196*256 = 50176 >= NNODES

// ================= scratch (static device globals) =================
__device__ int   g_rowptr[NNODES + 1];
__device__ int   g_cursor[NNODES];
__device__ int   g_scantmp[NNODES];
__device__ int   g_bsum[256];
__device__ int   g_srcs[ETOT_MAX];
__device__ __align__(16) float g_h[NNODES * HID];    // layer-1 transformed features
__device__ __align__(16) float g_h2[NNODES * HID];   // layer-2 transformed features
__device__ __align__(16) float g_x1[NNODES * HID];   // layer-1 aggregated output
__device__ __align__(16) float g_als[NNODES * NHEAD];
__device__ __align__(16) float g_ald[NNODES * NHEAD];
__device__ __align__(16) float g_als2[NNODES * NHEAD];
__device__ __align__(16) float g_ald2[NNODES * NHEAD];
// bf16 hi/lo split weights, stored [n][k]
__device__ __align__(16) __nv_bfloat16 g_b1hi[HID * 128];
__device__ __align__(16) __nv_bfloat16 g_b1lo[HID * 128];
__device__ __align__(16) __nv_bfloat16 g_b2hi[HID * HID];
__device__ __align__(16) __nv_bfloat16 g_b2lo[HID * HID];

// ================= prep: weight hi/lo split + rowptr zero (merged) =================
__global__ void prep_kernel(const float* __restrict__ W1, const float* __restrict__ W2) {
    int i = blockIdx.x * blockDim.x + threadIdx.x;
    const int n1 = 128 * HID;          // W1 elements
    const int n2 = HID * HID;          // W2 elements
    if (i < n1) {                      // W1 [128][256]
        int k = i / HID, n = i - k * HID;
        float x = W1[i];
        __nv_bfloat16 h = __float2bfloat16(x);
        g_b1hi[n * 128 + k] = h;
        g_b1lo[n * 128 + k] = __float2bfloat16(x - __bfloat162float(h));
    } else if (i < n1 + n2) {          // W2 [256][256]
        int j = i - n1;
        int k = j / HID, n = j - k * HID;
        float x = W2[j];
        __nv_bfloat16 h = __float2bfloat16(x);
        g_b2hi[n * HID + k] = h;
        g_b2lo[n * HID + k] = __float2bfloat16(x - __bfloat162float(h));
    } else if (i < n1 + n2 + NNODES + 1) {
        g_rowptr[i - n1 - n2] = 0;
    }
}

// ================= CSR build =================
__global__ void hist_kernel(const int* __restrict__ dst, int etot) {
    int i = blockIdx.x * blockDim.x + threadIdx.x;
    int n4 = etot >> 2;
    if (i < n4) {
        int4 d = ((const int4*)dst)[i];
        atomicAdd(&g_rowptr[d.x], 1);
        atomicAdd(&g_rowptr[d.y], 1);
        atomicAdd(&g_rowptr[d.z], 1);
        atomicAdd(&g_rowptr[d.w], 1);
    }
    int rem = etot - n4 * 4;
    if (i < rem) atomicAdd(&g_rowptr[dst[n4 * 4 + i]], 1);
}

__global__ void scan_local_kernel() {
    int t = threadIdx.x, i = blockIdx.x * 256 + t;
    int lane = t & 31, wid = t >> 5;
    int val = (i < NNODES) ? g_rowptr[i] : 0;
    int x = val;
    #pragma unroll
    for (int o = 1; o < 32; o <<= 1) {
        int y = __shfl_up_sync(0xffffffffu, x, o);
        if (lane >= o) x += y;
    }
    __shared__ int wsum[8];
    if (lane == 31) wsum[wid] = x;
    __syncthreads();
    if (t < 8) {
        int s = wsum[t];
        #pragma unroll
        for (int o = 1; o < 8; o <<= 1) {
            int y = __shfl_up_sync(0xffu, s, o);
            if (t >= o) s += y;
        }
        wsum[t] = s;
    }
    __syncthreads();
    int incl = x + (wid ? wsum[wid - 1] : 0);
    if (i < NNODES) g_scantmp[i] = incl - val;
    if (t == 255) g_bsum[blockIdx.x] = incl;
}

__global__ void scan_bsums_kernel() {
    int t = threadIdx.x;
    int lane = t & 31, wid = t >> 5;
    int val = (t < SCAN_NB) ? g_bsum[t] : 0;
    int x = val;
    #pragma unroll
    for (int o = 1; o < 32; o <<= 1) {
        int y = __shfl_up_sync(0xffffffffu, x, o);
        if (lane >= o) x += y;
    }
    __shared__ int wsum[8];
    if (lane == 31) wsum[wid] = x;
    __syncthreads();
    if (t < 8) {
        int s = wsum[t];
        #pragma unroll
        for (int o = 1; o < 8; o <<= 1) {
            int y = __shfl_up_sync(0xffu, s, o);
            if (t >= o) s += y;
        }
        wsum[t] = s;
    }
    __syncthreads();
    int incl = x + (wid ? wsum[wid - 1] : 0);
    if (t < SCAN_NB) g_bsum[t] = incl - val;
    if (t == 255) g_rowptr[NNODES] = incl;
}

__global__ void scan_add_kernel() {
    int i = blockIdx.x * 256 + threadIdx.x;
    if (i < NNODES) {
        int e = g_scantmp[i] + g_bsum[blockIdx.x];
        g_rowptr[i] = e;
        g_cursor[i] = e;
    }
}

__global__ void scatter_kernel(const int* __restrict__ src,
                               const int* __restrict__ dst, int etot) {
    int i = blockIdx.x * blockDim.x + threadIdx.x;
    int n4 = etot >> 2;
    if (i < n4) {
        int4 s = ((const int4*)src)[i];
        int4 d = ((const int4*)dst)[i];
        g_srcs[atomicAdd(&g_cursor[d.x], 1)] = s.x;
        g_srcs[atomicAdd(&g_cursor[d.y], 1)] = s.y;
        g_srcs[atomicAdd(&g_cursor[d.z], 1)] = s.z;
        g_srcs[atomicAdd(&g_cursor[d.w], 1)] = s.w;
    }
    int rem = etot - n4 * 4;
    if (i < rem) {
        int j = n4 * 4 + i;
        g_srcs[atomicAdd(&g_cursor[dst[j]], 1)] = src[j];
    }
}

// ================= bf16 mma.sync GEMM with fused attention logits =================
__device__ __forceinline__ void mma_bf16(float* c, const uint32_t* a, uint32_t b0, uint32_t b1) {
    asm volatile("mma.sync.aligned.m16n8k16.row.col.f32.bf16.bf16.f32 "
        "{%0,%1,%2,%3}, {%4,%5,%6,%7}, {%8,%9}, {%0,%1,%2,%3};"
        : "+f"(c[0]), "+f"(c[1]), "+f"(c[2]), "+f"(c[3])
        : "r"(a[0]), "r"(a[1]), "r"(a[2]), "r"(a[3]), "r"(b0), "r"(b1));
}

// layer 0: A = Aext (fp32, split on the fly), K=128, out = g_h/g_als/g_ald.
// layer 1: A = g_x1 (device-side select), K=256, out = g_h2/g_als2/g_ald2.
__global__ void __launch_bounds__(256)
gemm_mma_kernel(int layer, int M, const float* __restrict__ Aext,
                const float* __restrict__ asrc, const float* __restrict__ adst) {
    const int K = layer ? 256 : 128;
    const float* __restrict__ A = layer ? g_x1 : Aext;
    const __nv_bfloat16* __restrict__ bhi = layer ? g_b2hi : g_b1hi;
    const __nv_bfloat16* __restrict__ blo = layer ? g_b2lo : g_b1lo;
    float* __restrict__ Cout = layer ? g_h2 : g_h;
    float* __restrict__ alsO = layer ? g_als2 : g_als;
    float* __restrict__ aldO = layer ? g_ald2 : g_ald;

    __shared__ __nv_bfloat16 sAhi[128][40];
    __shared__ __nv_bfloat16 sAlo[128][40];
    __shared__ __nv_bfloat16 sBhi[128][40];
    __shared__ __nv_bfloat16 sBlo[128][40];

    const int tid = threadIdx.x, lane = tid & 31, wid = tid >> 5;
    const int wm = wid >> 2, wn = wid & 3;
    const int row0 = blockIdx.x * 128;
    const int n0 = blockIdx.y * 128;
    const int qid = lane >> 2, qlane = lane & 3;

    float c[4][4][4];
    #pragma unroll
    for (int i = 0; i < 4; i++)
        #pragma unroll
        for (int j = 0; j < 4; j++)
            #pragma unroll
            for (int k = 0; k < 4; k++) c[i][j][k] = 0.f;

    const int nkb = K >> 5;
    for (int kb = 0; kb < nkb; kb++) {
        #pragma unroll
        for (int i = 0; i < 4; i++) {
            int idx = tid + 256 * i;         // 0..1023
            int r = idx >> 3, kq = idx & 7;
            int gr = row0 + r;
            float4 v = make_float4(0.f, 0.f, 0.f, 0.f);
            if (gr < M) v = *(const float4*)&A[(size_t)gr * K + kb * 32 + kq * 4];
            __nv_bfloat162 h01 = __floats2bfloat162_rn(v.x, v.y);
            __nv_bfloat162 h23 = __floats2bfloat162_rn(v.z, v.w);
            __nv_bfloat162 l01 = __floats2bfloat162_rn(v.x - __low2float(h01),
                                                       v.y - __high2float(h01));
            __nv_bfloat162 l23 = __floats2bfloat162_rn(v.z - __low2float(h23),
                                                       v.w - __high2float(h23));
            *(uint2*)&sAhi[r][kq * 4] = make_uint2(*(uint32_t*)&h01, *(uint32_t*)&h23);
            *(uint2*)&sAlo[r][kq * 4] = make_uint2(*(uint32_t*)&l01, *(uint32_t*)&l23);
            size_t gb = (size_t)(n0 + r) * K + kb * 32 + kq * 4;
            *(uint2*)&sBhi[r][kq * 4] = *(const uint2*)&bhi[gb];
            *(uint2*)&sBlo[r][kq * 4] = *(const uint2*)&blo[gb];
        }
        __syncthreads();

        #pragma unroll
        for (int ks = 0; ks < 2; ks++) {
            const int k0 = ks * 16;
            uint32_t ah[4][4], al[4][4];
            #pragma unroll
            for (int mi = 0; mi < 4; mi++) {
                int r = wm * 64 + mi * 16 + qid;
                int cw = k0 + qlane * 2;
                ah[mi][0] = *(const uint32_t*)&sAhi[r][cw];
                ah[mi][1] = *(const uint32_t*)&sAhi[r + 8][cw];
                ah[mi][2] = *(const uint32_t*)&sAhi[r][cw + 8];
                ah[mi][3] = *(const uint32_t*)&sAhi[r + 8][cw + 8];
                al[mi][0] = *(const uint32_t*)&sAlo[r][cw];
                al[mi][1] = *(const uint32_t*)&sAlo[r + 8][cw];
                al[mi][2] = *(const uint32_t*)&sAlo[r][cw + 8];
                al[mi][3] = *(const uint32_t*)&sAlo[r + 8][cw + 8];
            }
            #pragma unroll
            for (int ni = 0; ni < 4; ni++) {
                int n = wn * 32 + ni * 8 + qid;
                int kw = k0 + qlane * 2;
                uint32_t bh0 = *(const uint32_t*)&sBhi[n][kw];
                uint32_t bh1 = *(const uint32_t*)&sBhi[n][kw + 8];
                uint32_t bl0 = *(const uint32_t*)&sBlo[n][kw];
                uint32_t bl1 = *(const uint32_t*)&sBlo[n][kw + 8];
                #pragma unroll
                for (int mi = 0; mi < 4; mi++) {
                    mma_bf16(c[mi][ni], ah[mi], bh0, bh1);
                    mma_bf16(c[mi][ni], ah[mi], bl0, bl1);
                    mma_bf16(c[mi][ni], al[mi], bh0, bh1);
                }
            }
        }
        __syncthreads();
    }

    // ---- fused attention logits (this warp's 32 cols == one head) ----
    const int head = (n0 >> 5) + wn;
    float as_v[4][2], ad_v[4][2];
    #pragma unroll
    for (int ni = 0; ni < 4; ni++)
        #pragma unroll
        for (int j = 0; j < 2; j++) {
            int col = head * 32 + ni * 8 + qlane * 2 + j;
            as_v[ni][j] = asrc[col];
            ad_v[ni][j] = adst[col];
        }
    #pragma unroll
    for (int mi = 0; mi < 4; mi++) {
        #pragma unroll
        for (int h = 0; h < 2; h++) {
            float ps = 0.f, pd = 0.f;
            #pragma unroll
            for (int ni = 0; ni < 4; ni++)
                #pragma unroll
                for (int j = 0; j < 2; j++) {
                    float v = c[mi][ni][h * 2 + j];
                    ps = fmaf(v, as_v[ni][j], ps);
                    pd = fmaf(v, ad_v[ni][j], pd);
                }
            ps += __shfl_xor_sync(0xffffffffu, ps, 1);
            ps += __shfl_xor_sync(0xffffffffu, ps, 2);
            pd += __shfl_xor_sync(0xffffffffu, pd, 1);
            pd += __shfl_xor_sync(0xffffffffu, pd, 2);
            int row = row0 + wm * 64 + mi * 16 + h * 8 + qid;
            if (qlane == 0 && row < M) {
                alsO[row * NHEAD + head] = ps;
                aldO[row * NHEAD + head] = pd;
            }
        }
    }
    // ---- store C ----
    #pragma unroll
    for (int mi = 0; mi < 4; mi++) {
        int r = row0 + wm * 64 + mi * 16 + qid;
        #pragma unroll
        for (int ni = 0; ni < 4; ni++) {
            int cg = n0 + wn * 32 + ni * 8 + qlane * 2;
            if (r < M)
                *(float2*)&Cout[(size_t)r * HID + cg] = make_float2(c[mi][ni][0], c[mi][ni][1]);
            if (r + 8 < M)
                *(float2*)&Cout[(size_t)(r + 8) * HID + cg] = make_float2(c[mi][ni][2], c[mi][ni][3]);
        }
    }
}

// ================= segmented softmax + aggregation + bias + ELU =================
// Weight phase: warp 0 only, one edge per lane, all 8 heads via two float4 logit loads.
// layer 0: read g_h/g_als/g_ald, write g_x1. layer 1: read g_h2/g_als2/g_ald2, write outp.
__global__ void __launch_bounds__(256)
gat_agg_kernel(const float* __restrict__ bias, float* __restrict__ outp, int layer) {
    const float* __restrict__ hbuf = layer ? g_h2 : g_h;
    const float* __restrict__ alsI = layer ? g_als2 : g_als;
    const float* __restrict__ aldI = layer ? g_ald2 : g_ald;

    int v = blockIdx.x;
    int tid = threadIdx.x, lane = tid & 31, warp = tid >> 5;
    int start = g_rowptr[v], end = g_rowptr[v + 1];

    __shared__ float sh_s[8];
    __shared__ float sh_w[8][32];
    __shared__ int   sh_src[32];
    __shared__ float4 sh_red[256];

    // per-lane (warp 0) partial sums for all 8 heads
    float ssum[8];
    #pragma unroll
    for (int h = 0; h < 8; h++) ssum[h] = 0.f;

    float4 d0, d1;
    if (warp == 0) {
        d0 = *(const float4*)&aldI[v * NHEAD];
        d1 = *(const float4*)&aldI[v * NHEAD + 4];
    }

    float4 acc = make_float4(0.f, 0.f, 0.f, 0.f);
    int cg = tid & 63;
    int sub = tid >> 6;
    int headc = cg >> 3;

    for (int t = start; t < end; t += 32) {
        int cnt = min(32, end - t);
        if (warp == 0 && lane < cnt) {
            int s = g_srcs[t + lane];
            sh_src[lane] = s;
            float4 a0 = *(const float4*)&alsI[s * NHEAD];
            float4 a1 = *(const float4*)&alsI[s * NHEAD + 4];
            float e[8] = { a0.x + d0.x, a0.y + d0.y, a0.z + d0.z, a0.w + d0.w,
                           a1.x + d1.x, a1.y + d1.y, a1.z + d1.z, a1.w + d1.w };
            #pragma unroll
            for (int h = 0; h < 8; h++) {
                float eh = (e[h] > 0.f) ? e[h] : 0.2f * e[h];
                float w = __expf(eh);
                sh_w[h][lane] = w;
                ssum[h] += w;
            }
        }
        __syncthreads();
        for (int j = sub; j < cnt; j += 4) {
            int s = sh_src[j];
            float w = sh_w[headc][j];
            const float4 hv = *reinterpret_cast<const float4*>(&hbuf[(size_t)s * HID + cg * 4]);
            acc.x = fmaf(w, hv.x, acc.x);
            acc.y = fmaf(w, hv.y, acc.y);
            acc.z = fmaf(w, hv.z, acc.z);
            acc.w = fmaf(w, hv.w, acc.w);
        }
        __syncthreads();
    }

    if (warp == 0) {
        #pragma unroll
        for (int h = 0; h < 8; h++) {
            float s = ssum[h];
            #pragma unroll
            for (int o = 16; o; o >>= 1) s += __shfl_xor_sync(0xffffffffu, s, o);
            if (lane == 0) sh_s[h] = s;
        }
    }

    sh_red[tid] = acc;
    __syncthreads();

    if (tid < 64) {
        float4 a0 = sh_red[tid];
        float4 a1 = sh_red[tid + 64];
        float4 a2 = sh_red[tid + 128];
        float4 a3 = sh_red[tid + 192];
        float r0 = a0.x + a1.x + a2.x + a3.x;
        float r1 = a0.y + a1.y + a2.y + a3.y;
        float r2 = a0.z + a1.z + a2.z + a3.z;
        float r3 = a0.w + a1.w + a2.w + a3.w;
        float inv = 1.f / (sh_s[tid >> 3] + 1e-16f);
        float vals[4] = { r0 * inv, r1 * inv, r2 * inv, r3 * inv };
        float* dstp = layer ? (outp + (size_t)v * HID) : (g_x1 + (size_t)v * HID);
        #pragma unroll
        for (int k = 0; k < 4; k++) {
            float val = vals[k] + bias[tid * 4 + k];
            val = (val > 0.f) ? val : (__expf(val) - 1.f);   // ELU
            dstp[tid * 4 + k] = val;
        }
    }
}

// ================= driver (round-8 schedule) =================
extern "C" void kernel_launch(void* const* d_in, const int* in_sizes, int n_in,
                              void* d_out, int out_size) {
    const float* x    = (const float*)d_in[0];
    const int*   ei   = (const int*)d_in[1];
    const float* W1   = (const float*)d_in[2];
    const float* a1s  = (const float*)d_in[3];
    const float* a1d  = (const float*)d_in[4];
    const float* b1   = (const float*)d_in[5];
    const float* W2   = (const float*)d_in[6];
    const float* a2s  = (const float*)d_in[7];
    const float* a2d  = (const float*)d_in[8];
    const float* b2   = (const float*)d_in[9];
    float* out = (float*)d_out;

    int etot = in_sizes[1] / 2;
    const int* src = ei;
    const int* dst = ei + etot;
    int eb4 = (etot / 4 + 255) / 256 + 1;

    static cudaStream_t s_side = nullptr;
    static cudaEvent_t ev_fork = nullptr, ev_join = nullptr;
    if (!s_side) {
        cudaStreamCreateWithFlags(&s_side, cudaStreamNonBlocking);
        cudaEventCreateWithFlags(&ev_fork, cudaEventDisableTiming);
        cudaEventCreateWithFlags(&ev_join, cudaEventDisableTiming);
    }

    // ---- main: weight split + rowptr zero (merged) ----
    const int prep_n = 128 * HID + HID * HID + NNODES + 1;
    prep_kernel<<<(prep_n + 255) / 256, 256>>>(W1, W2);

    // ---- fork: CSR build on side stream, concurrent with gemm1 ----
    cudaEventRecord(ev_fork, 0);
    cudaStreamWaitEvent(s_side, ev_fork, 0);
    hist_kernel<<<eb4, 256, 0, s_side>>>(dst, etot);
    scan_local_kernel<<<SCAN_NB, 256, 0, s_side>>>();
    scan_bsums_kernel<<<1, 256, 0, s_side>>>();
    scan_add_kernel<<<SCAN_NB, 256, 0, s_side>>>();
    scatter_kernel<<<eb4, 256, 0, s_side>>>(src, dst, etot);
    cudaEventRecord(ev_join, s_side);

    // ---- main: layer-1 GEMM (independent of CSR) ----
    dim3 ggrid((NNODES + 127) / 128, 2);
    gemm_mma_kernel<<<ggrid, 256>>>(0, NNODES, x, a1s, a1d);

    // ---- join, then the strictly-ordered tail ----
    cudaStreamWaitEvent(0, ev_join, 0);
    gat_agg_kernel<<<NNODES, 256>>>(b1, nullptr, 0);
    gemm_mma_kernel<<<ggrid, 256>>>(1, NNODES, nullptr, a2s, a2d);
    gat_agg_kernel<<<NNODES, 256>>>(b2, out, 1);
}

// round 13
// speedup vs baseline: 1.0613x; 1.0613x over previous
#include <cuda_runtime.h>
#include <cuda_bf16.h>
#include <cstdint>

#define NNODES   50000
#define ETOT_MAX 900000
#define HID      256
#define NHEAD    8
#define SCAN_NB  196          // 196*256 = 50176 >= NNODES

// ================= scratch (static device globals) =================
__device__ int   g_rowptr[NNODES + 1];
__device__ int   g_cursor[NNODES];
__device__ int   g_scantmp[NNODES];
__device__ int   g_bsum[256];
__device__ int   g_srcs[ETOT_MAX];
__device__ __align__(16) float g_h[NNODES * HID];    // layer-1 transformed features
__device__ __align__(16) float g_h2[NNODES * HID];   // layer-2 transformed features
__device__ __align__(16) float g_x1[NNODES * HID];   // layer-1 aggregated output
__device__ __align__(16) float g_als[NNODES * NHEAD];
__device__ __align__(16) float g_ald[NNODES * NHEAD];
__device__ __align__(16) float g_als2[NNODES * NHEAD];
__device__ __align__(16) float g_ald2[NNODES * NHEAD];
// bf16 hi/lo split weights, stored [n][k]
__device__ __align__(16) __nv_bfloat16 g_b1hi[HID * 128];
__device__ __align__(16) __nv_bfloat16 g_b1lo[HID * 128];
__device__ __align__(16) __nv_bfloat16 g_b2hi[HID * HID];
__device__ __align__(16) __nv_bfloat16 g_b2lo[HID * HID];

// ================= CSR build =================
__global__ void zero_counts_kernel() {
    int i = blockIdx.x * blockDim.x + threadIdx.x;
    if (i <= NNODES) g_rowptr[i] = 0;
}

__global__ void hist_kernel(const int* __restrict__ dst, int etot) {
    int i = blockIdx.x * blockDim.x + threadIdx.x;
    int n4 = etot >> 2;
    if (i < n4) {
        int4 d = ((const int4*)dst)[i];
        atomicAdd(&g_rowptr[d.x], 1);
        atomicAdd(&g_rowptr[d.y], 1);
        atomicAdd(&g_rowptr[d.z], 1);
        atomicAdd(&g_rowptr[d.w], 1);
    }
    int rem = etot - n4 * 4;
    if (i < rem) atomicAdd(&g_rowptr[dst[n4 * 4 + i]], 1);
}

__global__ void scan_local_kernel() {
    int t = threadIdx.x, i = blockIdx.x * 256 + t;
    int lane = t & 31, wid = t >> 5;
    int val = (i < NNODES) ? g_rowptr[i] : 0;
    int x = val;
    #pragma unroll
    for (int o = 1; o < 32; o <<= 1) {
        int y = __shfl_up_sync(0xffffffffu, x, o);
        if (lane >= o) x += y;
    }
    __shared__ int wsum[8];
    if (lane == 31) wsum[wid] = x;
    __syncthreads();
    if (t < 8) {
        int s = wsum[t];
        #pragma unroll
        for (int o = 1; o < 8; o <<= 1) {
            int y = __shfl_up_sync(0xffu, s, o);
            if (t >= o) s += y;
        }
        wsum[t] = s;
    }
    __syncthreads();
    int incl = x + (wid ? wsum[wid - 1] : 0);
    if (i < NNODES) g_scantmp[i] = incl - val;
    if (t == 255) g_bsum[blockIdx.x] = incl;
}

__global__ void scan_bsums_kernel() {
    int t = threadIdx.x;
    int lane = t & 31, wid = t >> 5;
    int val = (t < SCAN_NB) ? g_bsum[t] : 0;
    int x = val;
    #pragma unroll
    for (int o = 1; o < 32; o <<= 1) {
        int y = __shfl_up_sync(0xffffffffu, x, o);
        if (lane >= o) x += y;
    }
    __shared__ int wsum[8];
    if (lane == 31) wsum[wid] = x;
    __syncthreads();
    if (t < 8) {
        int s = wsum[t];
        #pragma unroll
        for (int o = 1; o < 8; o <<= 1) {
            int y = __shfl_up_sync(0xffu, s, o);
            if (t >= o) s += y;
        }
        wsum[t] = s;
    }
    __syncthreads();
    int incl = x + (wid ? wsum[wid - 1] : 0);
    if (t < SCAN_NB) g_bsum[t] = incl - val;
    if (t == 255) g_rowptr[NNODES] = incl;
}

__global__ void scan_add_kernel() {
    int i = blockIdx.x * 256 + threadIdx.x;
    if (i < NNODES) {
        int e = g_scantmp[i] + g_bsum[blockIdx.x];
        g_rowptr[i] = e;
        g_cursor[i] = e;
    }
}

__global__ void scatter_kernel(const int* __restrict__ src,
                               const int* __restrict__ dst, int etot) {
    int i = blockIdx.x * blockDim.x + threadIdx.x;
    int n4 = etot >> 2;
    if (i < n4) {
        int4 s = ((const int4*)src)[i];
        int4 d = ((const int4*)dst)[i];
        g_srcs[atomicAdd(&g_cursor[d.x], 1)] = s.x;
        g_srcs[atomicAdd(&g_cursor[d.y], 1)] = s.y;
        g_srcs[atomicAdd(&g_cursor[d.z], 1)] = s.z;
        g_srcs[atomicAdd(&g_cursor[d.w], 1)] = s.w;
    }
    int rem = etot - n4 * 4;
    if (i < rem) {
        int j = n4 * 4 + i;
        g_srcs[atomicAdd(&g_cursor[dst[j]], 1)] = src[j];
    }
}

// ================= weight fp32 -> bf16 hi/lo split =================
__global__ void convW_kernel(const float* __restrict__ W1, const float* __restrict__ W2) {
    int i = blockIdx.x * blockDim.x + threadIdx.x;
    const int n1 = 128 * HID;
    if (i < n1) {                       // W1 [128][256]
        int k = i / HID, n = i - k * HID;
        float x = W1[i];
        __nv_bfloat16 h = __float2bfloat16(x);
        g_b1hi[n * 128 + k] = h;
        g_b1lo[n * 128 + k] = __float2bfloat16(x - __bfloat162float(h));
    } else if (i < n1 + HID * HID) {    // W2 [256][256]
        int j = i - n1;
        int k = j / HID, n = j - k * HID;
        float x = W2[j];
        __nv_bfloat16 h = __float2bfloat16(x);
        g_b2hi[n * HID + k] = h;
        g_b2lo[n * HID + k] = __float2bfloat16(x - __bfloat162float(h));
    }
}

// ================= bf16 mma.sync GEMM with fused attention logits =================
__device__ __forceinline__ void mma_bf16(float* c, const uint32_t* a, uint32_t b0, uint32_t b1) {
    asm volatile("mma.sync.aligned.m16n8k16.row.col.f32.bf16.bf16.f32 "
        "{%0,%1,%2,%3}, {%4,%5,%6,%7}, {%8,%9}, {%0,%1,%2,%3};"
        : "+f"(c[0]), "+f"(c[1]), "+f"(c[2]), "+f"(c[3])
        : "r"(a[0]), "r"(a[1]), "r"(a[2]), "r"(a[3]), "r"(b0), "r"(b1));
}

// layer 0: A = Aext (fp32, split on the fly), K=128, out = g_h/g_als/g_ald.
// layer 1: A = g_x1 (device-side select), K=256, out = g_h2/g_als2/g_ald2.
__global__ void __launch_bounds__(256)
gemm_mma_kernel(int layer, int M, const float* __restrict__ Aext,
                const float* __restrict__ asrc, const float* __restrict__ adst) {
    const int K = layer ? 256 : 128;
    const float* __restrict__ A = layer ? g_x1 : Aext;
    const __nv_bfloat16* __restrict__ bhi = layer ? g_b2hi : g_b1hi;
    const __nv_bfloat16* __restrict__ blo = layer ? g_b2lo : g_b1lo;
    float* __restrict__ Cout = layer ? g_h2 : g_h;
    float* __restrict__ alsO = layer ? g_als2 : g_als;
    float* __restrict__ aldO = layer ? g_ald2 : g_ald;

    __shared__ __nv_bfloat16 sAhi[128][40];
    __shared__ __nv_bfloat16 sAlo[128][40];
    __shared__ __nv_bfloat16 sBhi[128][40];
    __shared__ __nv_bfloat16 sBlo[128][40];

    const int tid = threadIdx.x, lane = tid & 31, wid = tid >> 5;
    const int wm = wid >> 2, wn = wid & 3;
    const int row0 = blockIdx.x * 128;
    const int n0 = blockIdx.y * 128;
    const int qid = lane >> 2, qlane = lane & 3;

    float c[4][4][4];
    #pragma unroll
    for (int i = 0; i < 4; i++)
        #pragma unroll
        for (int j = 0; j < 4; j++)
            #pragma unroll
            for (int k = 0; k < 4; k++) c[i][j][k] = 0.f;

    const int nkb = K >> 5;
    for (int kb = 0; kb < nkb; kb++) {
        #pragma unroll
        for (int i = 0; i < 4; i++) {
            int idx = tid + 256 * i;         // 0..1023
            int r = idx >> 3, kq = idx & 7;
            int gr = row0 + r;
            float4 v = make_float4(0.f, 0.f, 0.f, 0.f);
            if (gr < M) v = *(const float4*)&A[(size_t)gr * K + kb * 32 + kq * 4];
            __nv_bfloat162 h01 = __floats2bfloat162_rn(v.x, v.y);
            __nv_bfloat162 h23 = __floats2bfloat162_rn(v.z, v.w);
            __nv_bfloat162 l01 = __floats2bfloat162_rn(v.x - __low2float(h01),
                                                       v.y - __high2float(h01));
            __nv_bfloat162 l23 = __floats2bfloat162_rn(v.z - __low2float(h23),
                                                       v.w - __high2float(h23));
            *(uint2*)&sAhi[r][kq * 4] = make_uint2(*(uint32_t*)&h01, *(uint32_t*)&h23);
            *(uint2*)&sAlo[r][kq * 4] = make_uint2(*(uint32_t*)&l01, *(uint32_t*)&l23);
            size_t gb = (size_t)(n0 + r) * K + kb * 32 + kq * 4;
            *(uint2*)&sBhi[r][kq * 4] = *(const uint2*)&bhi[gb];
            *(uint2*)&sBlo[r][kq * 4] = *(const uint2*)&blo[gb];
        }
        __syncthreads();

        #pragma unroll
        for (int ks = 0; ks < 2; ks++) {
            const int k0 = ks * 16;
            uint32_t ah[4][4], al[4][4];
            #pragma unroll
            for (int mi = 0; mi < 4; mi++) {
                int r = wm * 64 + mi * 16 + qid;
                int cw = k0 + qlane * 2;
                ah[mi][0] = *(const uint32_t*)&sAhi[r][cw];
                ah[mi][1] = *(const uint32_t*)&sAhi[r + 8][cw];
                ah[mi][2] = *(const uint32_t*)&sAhi[r][cw + 8];
                ah[mi][3] = *(const uint32_t*)&sAhi[r + 8][cw + 8];
                al[mi][0] = *(const uint32_t*)&sAlo[r][cw];
                al[mi][1] = *(const uint32_t*)&sAlo[r + 8][cw];
                al[mi][2] = *(const uint32_t*)&sAlo[r][cw + 8];
                al[mi][3] = *(const uint32_t*)&sAlo[r + 8][cw + 8];
            }
            #pragma unroll
            for (int ni = 0; ni < 4; ni++) {
                int n = wn * 32 + ni * 8 + qid;
                int kw = k0 + qlane * 2;
                uint32_t bh0 = *(const uint32_t*)&sBhi[n][kw];
                uint32_t bh1 = *(const uint32_t*)&sBhi[n][kw + 8];
                uint32_t bl0 = *(const uint32_t*)&sBlo[n][kw];
                uint32_t bl1 = *(const uint32_t*)&sBlo[n][kw + 8];
                #pragma unroll
                for (int mi = 0; mi < 4; mi++) {
                    mma_bf16(c[mi][ni], ah[mi], bh0, bh1);
                    mma_bf16(c[mi][ni], ah[mi], bl0, bl1);
                    mma_bf16(c[mi][ni], al[mi], bh0, bh1);
                }
            }
        }
        __syncthreads();
    }

    // ---- fused attention logits (this warp's 32 cols == one head) ----
    const int head = (n0 >> 5) + wn;
    float as_v[4][2], ad_v[4][2];
    #pragma unroll
    for (int ni = 0; ni < 4; ni++)
        #pragma unroll
        for (int j = 0; j < 2; j++) {
            int col = head * 32 + ni * 8 + qlane * 2 + j;
            as_v[ni][j] = asrc[col];
            ad_v[ni][j] = adst[col];
        }
    #pragma unroll
    for (int mi = 0; mi < 4; mi++) {
        #pragma unroll
        for (int h = 0; h < 2; h++) {
            float ps = 0.f, pd = 0.f;
            #pragma unroll
            for (int ni = 0; ni < 4; ni++)
                #pragma unroll
                for (int j = 0; j < 2; j++) {
                    float v = c[mi][ni][h * 2 + j];
                    ps = fmaf(v, as_v[ni][j], ps);
                    pd = fmaf(v, ad_v[ni][j], pd);
                }
            ps += __shfl_xor_sync(0xffffffffu, ps, 1);
            ps += __shfl_xor_sync(0xffffffffu, ps, 2);
            pd += __shfl_xor_sync(0xffffffffu, pd, 1);
            pd += __shfl_xor_sync(0xffffffffu, pd, 2);
            int row = row0 + wm * 64 + mi * 16 + h * 8 + qid;
            if (qlane == 0 && row < M) {
                alsO[row * NHEAD + head] = ps;
                aldO[row * NHEAD + head] = pd;
            }
        }
    }
    // ---- store C ----
    #pragma unroll
    for (int mi = 0; mi < 4; mi++) {
        int r = row0 + wm * 64 + mi * 16 + qid;
        #pragma unroll
        for (int ni = 0; ni < 4; ni++) {
            int cg = n0 + wn * 32 + ni * 8 + qlane * 2;
            if (r < M)
                *(float2*)&Cout[(size_t)r * HID + cg] = make_float2(c[mi][ni][0], c[mi][ni][1]);
            if (r + 8 < M)
                *(float2*)&Cout[(size_t)(r + 8) * HID + cg] = make_float2(c[mi][ni][2], c[mi][ni][3]);
        }
    }
}

// ================= segmented softmax + aggregation + bias + ELU =================
// Fully warp-local: warp h owns head h. No shared memory, no __syncthreads.
// Weight phase lane-per-edge; (w, src) redistributed to gather lanes via shfl.
// layer 0: read g_h/g_als/g_ald, write g_x1. layer 1: read g_h2/g_als2/g_ald2, write outp.
__global__ void __launch_bounds__(256)
gat_agg_kernel(const float* __restrict__ bias, float* __restrict__ outp, int layer) {
    const float* __restrict__ hbuf = layer ? g_h2 : g_h;
    const float* __restrict__ alsI = layer ? g_als2 : g_als;
    const float* __restrict__ aldI = layer ? g_ald2 : g_ald;

    const int v = blockIdx.x;
    const int tid = threadIdx.x, lane = tid & 31;
    const int h = tid >> 5;             // warp == head
    const int eg = lane >> 3;           // edge subgroup 0..3
    const int cgl = lane & 7;           // channel group within head (4 ch each)
    const int start = g_rowptr[v], end = g_rowptr[v + 1];

    const float aldv = aldI[v * NHEAD + h];

    float4 acc = make_float4(0.f, 0.f, 0.f, 0.f);
    float wsum = 0.f;

    for (int t = start; t < end; t += 32) {
        int cnt = min(32, end - t);
        // --- weight phase: lane j owns edge t+j ---
        int s = 0;
        float w = 0.f;
        if (lane < cnt) {
            s = g_srcs[t + lane];
            float e = alsI[s * NHEAD + h] + aldv;
            e = (e > 0.f) ? e : 0.2f * e;
            w = __expf(e);
        }
        // tile weight sum (butterfly; w=0 for inactive lanes)
        float ws = w;
        #pragma unroll
        for (int o = 16; o; o >>= 1) ws += __shfl_xor_sync(0xffffffffu, ws, o);
        wsum += ws;
        // --- gather phase: redistribute (w, s) via shfl, uniform trip count ---
        int niter = (cnt + 3) >> 2;
        for (int k = 0; k < niter; k++) {
            int j = k * 4 + eg;
            float wj = __shfl_sync(0xffffffffu, w, j & 31);
            int   sj = __shfl_sync(0xffffffffu, s, j & 31);
            if (j < cnt) {
                const float4 hv = *reinterpret_cast<const float4*>(
                    &hbuf[(size_t)sj * HID + h * 32 + cgl * 4]);
                acc.x = fmaf(wj, hv.x, acc.x);
                acc.y = fmaf(wj, hv.y, acc.y);
                acc.z = fmaf(wj, hv.z, acc.z);
                acc.w = fmaf(wj, hv.w, acc.w);
            }
        }
    }

    // reduce acc over the 4 edge subgroups (lanes differing in bits 3,4)
    #pragma unroll
    for (int o = 8; o <= 16; o <<= 1) {
        acc.x += __shfl_xor_sync(0xffffffffu, acc.x, o);
        acc.y += __shfl_xor_sync(0xffffffffu, acc.y, o);
        acc.z += __shfl_xor_sync(0xffffffffu, acc.z, o);
        acc.w += __shfl_xor_sync(0xffffffffu, acc.w, o);
    }

    if (lane < 8) {
        float inv = 1.f / (wsum + 1e-16f);
        int col = h * 32 + cgl * 4;
        const float4 b = *reinterpret_cast<const float4*>(&bias[col]);
        float4 o;
        o.x = acc.x * inv + b.x;
        o.y = acc.y * inv + b.y;
        o.z = acc.z * inv + b.z;
        o.w = acc.w * inv + b.w;
        o.x = (o.x > 0.f) ? o.x : (__expf(o.x) - 1.f);
        o.y = (o.y > 0.f) ? o.y : (__expf(o.y) - 1.f);
        o.z = (o.z > 0.f) ? o.z : (__expf(o.z) - 1.f);
        o.w = (o.w > 0.f) ? o.w : (__expf(o.w) - 1.f);
        float* dstp = layer ? (outp + (size_t)v * HID) : (g_x1 + (size_t)v * HID);
        *reinterpret_cast<float4*>(&dstp[col]) = o;
    }
}

// ================= driver (round-8 schedule) =================
extern "C" void kernel_launch(void* const* d_in, const int* in_sizes, int n_in,
                              void* d_out, int out_size) {
    const float* x    = (const float*)d_in[0];
    const int*   ei   = (const int*)d_in[1];
    const float* W1   = (const float*)d_in[2];
    const float* a1s  = (const float*)d_in[3];
    const float* a1d  = (const float*)d_in[4];
    const float* b1   = (const float*)d_in[5];
    const float* W2   = (const float*)d_in[6];
    const float* a2s  = (const float*)d_in[7];
    const float* a2d  = (const float*)d_in[8];
    const float* b2   = (const float*)d_in[9];
    float* out = (float*)d_out;

    int etot = in_sizes[1] / 2;
    const int* src = ei;
    const int* dst = ei + etot;
    int eb4 = (etot / 4 + 255) / 256 + 1;

    static cudaStream_t s_side = nullptr;
    static cudaEvent_t ev_fork = nullptr, ev_join = nullptr;
    if (!s_side) {
        cudaStreamCreateWithFlags(&s_side, cudaStreamNonBlocking);
        cudaEventCreateWithFlags(&ev_fork, cudaEventDisableTiming);
        cudaEventCreateWithFlags(&ev_join, cudaEventDisableTiming);
    }

    // ---- main: weight split (needed by gemm1) ----
    convW_kernel<<<(128 * HID + HID * HID + 255) / 256, 256>>>(W1, W2);

    // ---- fork: CSR build on side stream, concurrent with gemm1 ----
    cudaEventRecord(ev_fork, 0);
    cudaStreamWaitEvent(s_side, ev_fork, 0);
    zero_counts_kernel<<<(NNODES + 256) / 256, 256, 0, s_side>>>();
    hist_kernel<<<eb4, 256, 0, s_side>>>(dst, etot);
    scan_local_kernel<<<SCAN_NB, 256, 0, s_side>>>();
    scan_bsums_kernel<<<1, 256, 0, s_side>>>();
    scan_add_kernel<<<SCAN_NB, 256, 0, s_side>>>();
    scatter_kernel<<<eb4, 256, 0, s_side>>>(src, dst, etot);
    cudaEventRecord(ev_join, s_side);

    // ---- main: layer-1 GEMM (independent of CSR) ----
    dim3 ggrid((NNODES + 127) / 128, 2);
    gemm_mma_kernel<<<ggrid, 256>>>(0, NNODES, x, a1s, a1d);

    // ---- join, then the strictly-ordered tail ----
    cudaStreamWaitEvent(0, ev_join, 0);
    gat_agg_kernel<<<NNODES, 256>>>(b1, nullptr, 0);
    gemm_mma_kernel<<<ggrid, 256>>>(1, NNODES, nullptr, a2s, a2d);
    gat_agg_kernel<<<NNODES, 256>>>(b2, out, 1);
}

// round 14
// speedup vs baseline: 1.2259x; 1.1551x over previous
#include <cuda_runtime.h>
#include <cuda_bf16.h>
#include <cuda_fp16.h>
#include <cstdint>

#define NNODES   50000
#define ETOT_MAX 900000
#define HID      256
#define NHEAD    8
#define SCAN_NB  196          // 196*256 = 50176 >= NNODES

// ================= scratch (static device globals) =================
__device__ int   g_rowptr[NNODES + 1];
__device__ int   g_cursor[NNODES];
__device__ int   g_scantmp[NNODES];
__device__ int   g_bsum[256];
__device__ int   g_srcs[ETOT_MAX];
__device__ __align__(16) __half g_h[NNODES * HID];   // layer-1 features (fp16 for gather BW)
__device__ __align__(16) __half g_h2[NNODES * HID];  // layer-2 features
__device__ __align__(16) float g_x1[NNODES * HID];   // layer-1 aggregated output (fp32)
__device__ __align__(16) float g_als[NNODES * NHEAD];
__device__ __align__(16) float g_ald[NNODES * NHEAD];
__device__ __align__(16) float g_als2[NNODES * NHEAD];
__device__ __align__(16) float g_ald2[NNODES * NHEAD];
// bf16 hi/lo split weights, stored [n][k]
__device__ __align__(16) __nv_bfloat16 g_b1hi[HID * 128];
__device__ __align__(16) __nv_bfloat16 g_b1lo[HID * 128];
__device__ __align__(16) __nv_bfloat16 g_b2hi[HID * HID];
__device__ __align__(16) __nv_bfloat16 g_b2lo[HID * HID];

// ================= CSR build =================
__global__ void zero_counts_kernel() {
    int i = blockIdx.x * blockDim.x + threadIdx.x;
    if (i <= NNODES) g_rowptr[i] = 0;
}

__global__ void hist_kernel(const int* __restrict__ dst, int etot) {
    int i = blockIdx.x * blockDim.x + threadIdx.x;
    int n4 = etot >> 2;
    if (i < n4) {
        int4 d = ((const int4*)dst)[i];
        atomicAdd(&g_rowptr[d.x], 1);
        atomicAdd(&g_rowptr[d.y], 1);
        atomicAdd(&g_rowptr[d.z], 1);
        atomicAdd(&g_rowptr[d.w], 1);
    }
    int rem = etot - n4 * 4;
    if (i < rem) atomicAdd(&g_rowptr[dst[n4 * 4 + i]], 1);
}

__global__ void scan_local_kernel() {
    int t = threadIdx.x, i = blockIdx.x * 256 + t;
    int lane = t & 31, wid = t >> 5;
    int val = (i < NNODES) ? g_rowptr[i] : 0;
    int x = val;
    #pragma unroll
    for (int o = 1; o < 32; o <<= 1) {
        int y = __shfl_up_sync(0xffffffffu, x, o);
        if (lane >= o) x += y;
    }
    __shared__ int wsum[8];
    if (lane == 31) wsum[wid] = x;
    __syncthreads();
    if (t < 8) {
        int s = wsum[t];
        #pragma unroll
        for (int o = 1; o < 8; o <<= 1) {
            int y = __shfl_up_sync(0xffu, s, o);
            if (t >= o) s += y;
        }
        wsum[t] = s;
    }
    __syncthreads();
    int incl = x + (wid ? wsum[wid - 1] : 0);
    if (i < NNODES) g_scantmp[i] = incl - val;
    if (t == 255) g_bsum[blockIdx.x] = incl;
}

__global__ void scan_bsums_kernel() {
    int t = threadIdx.x;
    int lane = t & 31, wid = t >> 5;
    int val = (t < SCAN_NB) ? g_bsum[t] : 0;
    int x = val;
    #pragma unroll
    for (int o = 1; o < 32; o <<= 1) {
        int y = __shfl_up_sync(0xffffffffu, x, o);
        if (lane >= o) x += y;
    }
    __shared__ int wsum[8];
    if (lane == 31) wsum[wid] = x;
    __syncthreads();
    if (t < 8) {
        int s = wsum[t];
        #pragma unroll
        for (int o = 1; o < 8; o <<= 1) {
            int y = __shfl_up_sync(0xffu, s, o);
            if (t >= o) s += y;
        }
        wsum[t] = s;
    }
    __syncthreads();
    int incl = x + (wid ? wsum[wid - 1] : 0);
    if (t < SCAN_NB) g_bsum[t] = incl - val;
    if (t == 255) g_rowptr[NNODES] = incl;
}

__global__ void scan_add_kernel() {
    int i = blockIdx.x * 256 + threadIdx.x;
    if (i < NNODES) {
        int e = g_scantmp[i] + g_bsum[blockIdx.x];
        g_rowptr[i] = e;
        g_cursor[i] = e;
    }
}

__global__ void scatter_kernel(const int* __restrict__ src,
                               const int* __restrict__ dst, int etot) {
    int i = blockIdx.x * blockDim.x + threadIdx.x;
    int n4 = etot >> 2;
    if (i < n4) {
        int4 s = ((const int4*)src)[i];
        int4 d = ((const int4*)dst)[i];
        g_srcs[atomicAdd(&g_cursor[d.x], 1)] = s.x;
        g_srcs[atomicAdd(&g_cursor[d.y], 1)] = s.y;
        g_srcs[atomicAdd(&g_cursor[d.z], 1)] = s.z;
        g_srcs[atomicAdd(&g_cursor[d.w], 1)] = s.w;
    }
    int rem = etot - n4 * 4;
    if (i < rem) {
        int j = n4 * 4 + i;
        g_srcs[atomicAdd(&g_cursor[dst[j]], 1)] = src[j];
    }
}

// ================= weight fp32 -> bf16 hi/lo split =================
__global__ void convW_kernel(const float* __restrict__ W1, const float* __restrict__ W2) {
    int i = blockIdx.x * blockDim.x + threadIdx.x;
    const int n1 = 128 * HID;
    if (i < n1) {                       // W1 [128][256]
        int k = i / HID, n = i - k * HID;
        float x = W1[i];
        __nv_bfloat16 h = __float2bfloat16(x);
        g_b1hi[n * 128 + k] = h;
        g_b1lo[n * 128 + k] = __float2bfloat16(x - __bfloat162float(h));
    } else if (i < n1 + HID * HID) {    // W2 [256][256]
        int j = i - n1;
        int k = j / HID, n = j - k * HID;
        float x = W2[j];
        __nv_bfloat16 h = __float2bfloat16(x);
        g_b2hi[n * HID + k] = h;
        g_b2lo[n * HID + k] = __float2bfloat16(x - __bfloat162float(h));
    }
}

// ================= bf16 mma.sync GEMM with fused attention logits =================
__device__ __forceinline__ void mma_bf16(float* c, const uint32_t* a, uint32_t b0, uint32_t b1) {
    asm volatile("mma.sync.aligned.m16n8k16.row.col.f32.bf16.bf16.f32 "
        "{%0,%1,%2,%3}, {%4,%5,%6,%7}, {%8,%9}, {%0,%1,%2,%3};"
        : "+f"(c[0]), "+f"(c[1]), "+f"(c[2]), "+f"(c[3])
        : "r"(a[0]), "r"(a[1]), "r"(a[2]), "r"(a[3]), "r"(b0), "r"(b1));
}

// layer 0: A = Aext (fp32, split on the fly), K=128, out = g_h/g_als/g_ald.
// layer 1: A = g_x1 (device-side select), K=256, out = g_h2/g_als2/g_ald2.
__global__ void __launch_bounds__(256)
gemm_mma_kernel(int layer, int M, const float* __restrict__ Aext,
                const float* __restrict__ asrc, const float* __restrict__ adst) {
    const int K = layer ? 256 : 128;
    const float* __restrict__ A = layer ? g_x1 : Aext;
    const __nv_bfloat16* __restrict__ bhi = layer ? g_b2hi : g_b1hi;
    const __nv_bfloat16* __restrict__ blo = layer ? g_b2lo : g_b1lo;
    __half* __restrict__ Cout = layer ? g_h2 : g_h;
    float* __restrict__ alsO = layer ? g_als2 : g_als;
    float* __restrict__ aldO = layer ? g_ald2 : g_ald;

    __shared__ __nv_bfloat16 sAhi[128][40];
    __shared__ __nv_bfloat16 sAlo[128][40];
    __shared__ __nv_bfloat16 sBhi[128][40];
    __shared__ __nv_bfloat16 sBlo[128][40];

    const int tid = threadIdx.x, lane = tid & 31, wid = tid >> 5;
    const int wm = wid >> 2, wn = wid & 3;
    const int row0 = blockIdx.x * 128;
    const int n0 = blockIdx.y * 128;
    const int qid = lane >> 2, qlane = lane & 3;

    float c[4][4][4];
    #pragma unroll
    for (int i = 0; i < 4; i++)
        #pragma unroll
        for (int j = 0; j < 4; j++)
            #pragma unroll
            for (int k = 0; k < 4; k++) c[i][j][k] = 0.f;

    const int nkb = K >> 5;
    for (int kb = 0; kb < nkb; kb++) {
        #pragma unroll
        for (int i = 0; i < 4; i++) {
            int idx = tid + 256 * i;         // 0..1023
            int r = idx >> 3, kq = idx & 7;
            int gr = row0 + r;
            float4 v = make_float4(0.f, 0.f, 0.f, 0.f);
            if (gr < M) v = *(const float4*)&A[(size_t)gr * K + kb * 32 + kq * 4];
            __nv_bfloat162 h01 = __floats2bfloat162_rn(v.x, v.y);
            __nv_bfloat162 h23 = __floats2bfloat162_rn(v.z, v.w);
            __nv_bfloat162 l01 = __floats2bfloat162_rn(v.x - __low2float(h01),
                                                       v.y - __high2float(h01));
            __nv_bfloat162 l23 = __floats2bfloat162_rn(v.z - __low2float(h23),
                                                       v.w - __high2float(h23));
            *(uint2*)&sAhi[r][kq * 4] = make_uint2(*(uint32_t*)&h01, *(uint32_t*)&h23);
            *(uint2*)&sAlo[r][kq * 4] = make_uint2(*(uint32_t*)&l01, *(uint32_t*)&l23);
            size_t gb = (size_t)(n0 + r) * K + kb * 32 + kq * 4;
            *(uint2*)&sBhi[r][kq * 4] = *(const uint2*)&bhi[gb];
            *(uint2*)&sBlo[r][kq * 4] = *(const uint2*)&blo[gb];
        }
        __syncthreads();

        #pragma unroll
        for (int ks = 0; ks < 2; ks++) {
            const int k0 = ks * 16;
            uint32_t ah[4][4], al[4][4];
            #pragma unroll
            for (int mi = 0; mi < 4; mi++) {
                int r = wm * 64 + mi * 16 + qid;
                int cw = k0 + qlane * 2;
                ah[mi][0] = *(const uint32_t*)&sAhi[r][cw];
                ah[mi][1] = *(const uint32_t*)&sAhi[r + 8][cw];
                ah[mi][2] = *(const uint32_t*)&sAhi[r][cw + 8];
                ah[mi][3] = *(const uint32_t*)&sAhi[r + 8][cw + 8];
                al[mi][0] = *(const uint32_t*)&sAlo[r][cw];
                al[mi][1] = *(const uint32_t*)&sAlo[r + 8][cw];
                al[mi][2] = *(const uint32_t*)&sAlo[r][cw + 8];
                al[mi][3] = *(const uint32_t*)&sAlo[r + 8][cw + 8];
            }
            #pragma unroll
            for (int ni = 0; ni < 4; ni++) {
                int n = wn * 32 + ni * 8 + qid;
                int kw = k0 + qlane * 2;
                uint32_t bh0 = *(const uint32_t*)&sBhi[n][kw];
                uint32_t bh1 = *(const uint32_t*)&sBhi[n][kw + 8];
                uint32_t bl0 = *(const uint32_t*)&sBlo[n][kw];
                uint32_t bl1 = *(const uint32_t*)&sBlo[n][kw + 8];
                #pragma unroll
                for (int mi = 0; mi < 4; mi++) {
                    mma_bf16(c[mi][ni], ah[mi], bh0, bh1);
                    mma_bf16(c[mi][ni], ah[mi], bl0, bl1);
                    mma_bf16(c[mi][ni], al[mi], bh0, bh1);
                }
            }
        }
        __syncthreads();
    }

    // ---- fused attention logits (fp32, from accumulators — unaffected by fp16 store) ----
    const int head = (n0 >> 5) + wn;
    float as_v[4][2], ad_v[4][2];
    #pragma unroll
    for (int ni = 0; ni < 4; ni++)
        #pragma unroll
        for (int j = 0; j < 2; j++) {
            int col = head * 32 + ni * 8 + qlane * 2 + j;
            as_v[ni][j] = asrc[col];
            ad_v[ni][j] = adst[col];
        }
    #pragma unroll
    for (int mi = 0; mi < 4; mi++) {
        #pragma unroll
        for (int h = 0; h < 2; h++) {
            float ps = 0.f, pd = 0.f;
            #pragma unroll
            for (int ni = 0; ni < 4; ni++)
                #pragma unroll
                for (int j = 0; j < 2; j++) {
                    float v = c[mi][ni][h * 2 + j];
                    ps = fmaf(v, as_v[ni][j], ps);
                    pd = fmaf(v, ad_v[ni][j], pd);
                }
            ps += __shfl_xor_sync(0xffffffffu, ps, 1);
            ps += __shfl_xor_sync(0xffffffffu, ps, 2);
            pd += __shfl_xor_sync(0xffffffffu, pd, 1);
            pd += __shfl_xor_sync(0xffffffffu, pd, 2);
            int row = row0 + wm * 64 + mi * 16 + h * 8 + qid;
            if (qlane == 0 && row < M) {
                alsO[row * NHEAD + head] = ps;
                aldO[row * NHEAD + head] = pd;
            }
        }
    }
    // ---- store C as fp16 (halves gather + store traffic) ----
    #pragma unroll
    for (int mi = 0; mi < 4; mi++) {
        int r = row0 + wm * 64 + mi * 16 + qid;
        #pragma unroll
        for (int ni = 0; ni < 4; ni++) {
            int cg = n0 + wn * 32 + ni * 8 + qlane * 2;
            if (r < M)
                *(__half2*)&Cout[(size_t)r * HID + cg] = __floats2half2_rn(c[mi][ni][0], c[mi][ni][1]);
            if (r + 8 < M)
                *(__half2*)&Cout[(size_t)(r + 8) * HID + cg] = __floats2half2_rn(c[mi][ni][2], c[mi][ni][3]);
        }
    }
}

// ================= segmented softmax + aggregation + bias + ELU =================
// Round-8 structure (proven optimum); gather now reads fp16 (8B per 4 channels).
// layer 0: read g_h/g_als/g_ald, write g_x1. layer 1: read g_h2/g_als2/g_ald2, write outp.
__global__ void __launch_bounds__(256)
gat_agg_kernel(const float* __restrict__ bias, float* __restrict__ outp, int layer) {
    const __half* __restrict__ hbuf = layer ? g_h2 : g_h;
    const float* __restrict__ alsI = layer ? g_als2 : g_als;
    const float* __restrict__ aldI = layer ? g_ald2 : g_ald;

    int v = blockIdx.x;
    int tid = threadIdx.x, lane = tid & 31, warp = tid >> 5;
    int start = g_rowptr[v], end = g_rowptr[v + 1];

    __shared__ float sh_s[8];
    __shared__ float sh_w[8][32];
    __shared__ int   sh_src[32];
    __shared__ float4 sh_red[256];

    float aldv = aldI[v * NHEAD + warp];

    float ssum = 0.f;
    float4 acc = make_float4(0.f, 0.f, 0.f, 0.f);
    int cg = tid & 63;          // 64 channel-groups of 4 channels
    int sub = tid >> 6;         // 4 concurrent edge sub-streams
    int headc = cg >> 3;        // head owning these channels

    for (int t = start; t < end; t += 32) {
        int cnt = min(32, end - t);
        if (lane < cnt) {
            int s = g_srcs[t + lane];
            if (warp == 0) sh_src[lane] = s;
            float e = alsI[s * NHEAD + warp] + aldv;
            e = (e > 0.f) ? e : 0.2f * e;
            float w = __expf(e);
            sh_w[warp][lane] = w;
            ssum += w;
        }
        __syncthreads();
        for (int j = sub; j < cnt; j += 4) {
            int s = sh_src[j];
            float w = sh_w[headc][j];
            uint2 raw = *reinterpret_cast<const uint2*>(&hbuf[(size_t)s * HID + cg * 4]);
            float2 f01 = __half22float2(*reinterpret_cast<__half2*>(&raw.x));
            float2 f23 = __half22float2(*reinterpret_cast<__half2*>(&raw.y));
            acc.x = fmaf(w, f01.x, acc.x);
            acc.y = fmaf(w, f01.y, acc.y);
            acc.z = fmaf(w, f23.x, acc.z);
            acc.w = fmaf(w, f23.y, acc.w);
        }
        __syncthreads();
    }

    #pragma unroll
    for (int o = 16; o; o >>= 1) ssum += __shfl_xor_sync(0xffffffffu, ssum, o);
    if (lane == 0) sh_s[warp] = ssum;

    sh_red[tid] = acc;
    __syncthreads();

    if (tid < 64) {
        float4 a0 = sh_red[tid];
        float4 a1 = sh_red[tid + 64];
        float4 a2 = sh_red[tid + 128];
        float4 a3 = sh_red[tid + 192];
        float r0 = a0.x + a1.x + a2.x + a3.x;
        float r1 = a0.y + a1.y + a2.y + a3.y;
        float r2 = a0.z + a1.z + a2.z + a3.z;
        float r3 = a0.w + a1.w + a2.w + a3.w;
        float inv = 1.f / (sh_s[tid >> 3] + 1e-16f);
        float vals[4] = { r0 * inv, r1 * inv, r2 * inv, r3 * inv };
        float* dstp = layer ? (outp + (size_t)v * HID) : (g_x1 + (size_t)v * HID);
        #pragma unroll
        for (int k = 0; k < 4; k++) {
            float val = vals[k] + bias[tid * 4 + k];
            val = (val > 0.f) ? val : (__expf(val) - 1.f);   // ELU
            dstp[tid * 4 + k] = val;
        }
    }
}

// ================= driver (round-8 schedule) =================
extern "C" void kernel_launch(void* const* d_in, const int* in_sizes, int n_in,
                              void* d_out, int out_size) {
    const float* x    = (const float*)d_in[0];
    const int*   ei   = (const int*)d_in[1];
    const float* W1   = (const float*)d_in[2];
    const float* a1s  = (const float*)d_in[3];
    const float* a1d  = (const float*)d_in[4];
    const float* b1   = (const float*)d_in[5];
    const float* W2   = (const float*)d_in[6];
    const float* a2s  = (const float*)d_in[7];
    const float* a2d  = (const float*)d_in[8];
    const float* b2   = (const float*)d_in[9];
    float* out = (float*)d_out;

    int etot = in_sizes[1] / 2;
    const int* src = ei;
    const int* dst = ei + etot;
    int eb4 = (etot / 4 + 255) / 256 + 1;

    static cudaStream_t s_side = nullptr;
    static cudaEvent_t ev_fork = nullptr, ev_join = nullptr;
    if (!s_side) {
        cudaStreamCreateWithFlags(&s_side, cudaStreamNonBlocking);
        cudaEventCreateWithFlags(&ev_fork, cudaEventDisableTiming);
        cudaEventCreateWithFlags(&ev_join, cudaEventDisableTiming);
    }

    // ---- main: weight split (needed by gemm1) ----
    convW_kernel<<<(128 * HID + HID * HID + 255) / 256, 256>>>(W1, W2);

    // ---- fork: CSR build on side stream, concurrent with gemm1 ----
    cudaEventRecord(ev_fork, 0);
    cudaStreamWaitEvent(s_side, ev_fork, 0);
    zero_counts_kernel<<<(NNODES + 256) / 256, 256, 0, s_side>>>();
    hist_kernel<<<eb4, 256, 0, s_side>>>(dst, etot);
    scan_local_kernel<<<SCAN_NB, 256, 0, s_side>>>();
    scan_bsums_kernel<<<1, 256, 0, s_side>>>();
    scan_add_kernel<<<SCAN_NB, 256, 0, s_side>>>();
    scatter_kernel<<<eb4, 256, 0, s_side>>>(src, dst, etot);
    cudaEventRecord(ev_join, s_side);

    // ---- main: layer-1 GEMM (independent of CSR) ----
    dim3 ggrid((NNODES + 127) / 128, 2);
    gemm_mma_kernel<<<ggrid, 256>>>(0, NNODES, x, a1s, a1d);

    // ---- join, then the strictly-ordered tail ----
    cudaStreamWaitEvent(0, ev_join, 0);
    gat_agg_kernel<<<NNODES, 256>>>(b1, nullptr, 0);
    gemm_mma_kernel<<<ggrid, 256>>>(1, NNODES, nullptr, a2s, a2d);
    gat_agg_kernel<<<NNODES, 256>>>(b2, out, 1);
}

// round 15
// speedup vs baseline: 1.2269x; 1.0008x over previous
#include <cuda_runtime.h>
#include <cuda_bf16.h>
#include <cuda_fp16.h>
#include <cstdint>

#define NNODES   50000
#define ETOT_MAX 900000
#define HID      256
#define NHEAD    8
#define SCAN_NB  196          // 196*256 = 50176 >= NNODES
#define AGG_GRID 1184         // 148 SMs * 8 resident CTAs

// ================= scratch (static device globals) =================
__device__ int   g_rowptr[NNODES + 1];
__device__ int   g_cursor[NNODES];
__device__ int   g_scantmp[NNODES];
__device__ int   g_bsum[256];
__device__ int   g_srcs[ETOT_MAX];
__device__ __align__(16) __half g_h[NNODES * HID];   // layer-1 features (fp16 for gather BW)
__device__ __align__(16) __half g_h2[NNODES * HID];  // layer-2 features
__device__ __align__(16) float g_x1[NNODES * HID];   // layer-1 aggregated output (fp32)
__device__ __align__(16) float g_als[NNODES * NHEAD];
__device__ __align__(16) float g_ald[NNODES * NHEAD];
__device__ __align__(16) float g_als2[NNODES * NHEAD];
__device__ __align__(16) float g_ald2[NNODES * NHEAD];
// bf16 hi/lo split weights, stored [n][k]
__device__ __align__(16) __nv_bfloat16 g_b1hi[HID * 128];
__device__ __align__(16) __nv_bfloat16 g_b1lo[HID * 128];
__device__ __align__(16) __nv_bfloat16 g_b2hi[HID * HID];
__device__ __align__(16) __nv_bfloat16 g_b2lo[HID * HID];

// ================= CSR build =================
__global__ void zero_counts_kernel() {
    int i = blockIdx.x * blockDim.x + threadIdx.x;
    if (i <= NNODES) g_rowptr[i] = 0;
}

__global__ void hist_kernel(const int* __restrict__ dst, int etot) {
    int i = blockIdx.x * blockDim.x + threadIdx.x;
    int n4 = etot >> 2;
    if (i < n4) {
        int4 d = ((const int4*)dst)[i];
        atomicAdd(&g_rowptr[d.x], 1);
        atomicAdd(&g_rowptr[d.y], 1);
        atomicAdd(&g_rowptr[d.z], 1);
        atomicAdd(&g_rowptr[d.w], 1);
    }
    int rem = etot - n4 * 4;
    if (i < rem) atomicAdd(&g_rowptr[dst[n4 * 4 + i]], 1);
}

__global__ void scan_local_kernel() {
    int t = threadIdx.x, i = blockIdx.x * 256 + t;
    int lane = t & 31, wid = t >> 5;
    int val = (i < NNODES) ? g_rowptr[i] : 0;
    int x = val;
    #pragma unroll
    for (int o = 1; o < 32; o <<= 1) {
        int y = __shfl_up_sync(0xffffffffu, x, o);
        if (lane >= o) x += y;
    }
    __shared__ int wsum[8];
    if (lane == 31) wsum[wid] = x;
    __syncthreads();
    if (t < 8) {
        int s = wsum[t];
        #pragma unroll
        for (int o = 1; o < 8; o <<= 1) {
            int y = __shfl_up_sync(0xffu, s, o);
            if (t >= o) s += y;
        }
        wsum[t] = s;
    }
    __syncthreads();
    int incl = x + (wid ? wsum[wid - 1] : 0);
    if (i < NNODES) g_scantmp[i] = incl - val;
    if (t == 255) g_bsum[blockIdx.x] = incl;
}

__global__ void scan_bsums_kernel() {
    int t = threadIdx.x;
    int lane = t & 31, wid = t >> 5;
    int val = (t < SCAN_NB) ? g_bsum[t] : 0;
    int x = val;
    #pragma unroll
    for (int o = 1; o < 32; o <<= 1) {
        int y = __shfl_up_sync(0xffffffffu, x, o);
        if (lane >= o) x += y;
    }
    __shared__ int wsum[8];
    if (lane == 31) wsum[wid] = x;
    __syncthreads();
    if (t < 8) {
        int s = wsum[t];
        #pragma unroll
        for (int o = 1; o < 8; o <<= 1) {
            int y = __shfl_up_sync(0xffu, s, o);
            if (t >= o) s += y;
        }
        wsum[t] = s;
    }
    __syncthreads();
    int incl = x + (wid ? wsum[wid - 1] : 0);
    if (t < SCAN_NB) g_bsum[t] = incl - val;
    if (t == 255) g_rowptr[NNODES] = incl;
}

__global__ void scan_add_kernel() {
    int i = blockIdx.x * 256 + threadIdx.x;
    if (i < NNODES) {
        int e = g_scantmp[i] + g_bsum[blockIdx.x];
        g_rowptr[i] = e;
        g_cursor[i] = e;
    }
}

__global__ void scatter_kernel(const int* __restrict__ src,
                               const int* __restrict__ dst, int etot) {
    int i = blockIdx.x * blockDim.x + threadIdx.x;
    int n4 = etot >> 2;
    if (i < n4) {
        int4 s = ((const int4*)src)[i];
        int4 d = ((const int4*)dst)[i];
        g_srcs[atomicAdd(&g_cursor[d.x], 1)] = s.x;
        g_srcs[atomicAdd(&g_cursor[d.y], 1)] = s.y;
        g_srcs[atomicAdd(&g_cursor[d.z], 1)] = s.z;
        g_srcs[atomicAdd(&g_cursor[d.w], 1)] = s.w;
    }
    int rem = etot - n4 * 4;
    if (i < rem) {
        int j = n4 * 4 + i;
        g_srcs[atomicAdd(&g_cursor[dst[j]], 1)] = src[j];
    }
}

// ================= weight fp32 -> bf16 hi/lo split =================
__global__ void convW_kernel(const float* __restrict__ W1, const float* __restrict__ W2) {
    int i = blockIdx.x * blockDim.x + threadIdx.x;
    const int n1 = 128 * HID;
    if (i < n1) {                       // W1 [128][256]
        int k = i / HID, n = i - k * HID;
        float x = W1[i];
        __nv_bfloat16 h = __float2bfloat16(x);
        g_b1hi[n * 128 + k] = h;
        g_b1lo[n * 128 + k] = __float2bfloat16(x - __bfloat162float(h));
    } else if (i < n1 + HID * HID) {    // W2 [256][256]
        int j = i - n1;
        int k = j / HID, n = j - k * HID;
        float x = W2[j];
        __nv_bfloat16 h = __float2bfloat16(x);
        g_b2hi[n * HID + k] = h;
        g_b2lo[n * HID + k] = __float2bfloat16(x - __bfloat162float(h));
    }
}

// ================= bf16 mma.sync GEMM with fused attention logits =================
__device__ __forceinline__ void mma_bf16(float* c, const uint32_t* a, uint32_t b0, uint32_t b1) {
    asm volatile("mma.sync.aligned.m16n8k16.row.col.f32.bf16.bf16.f32 "
        "{%0,%1,%2,%3}, {%4,%5,%6,%7}, {%8,%9}, {%0,%1,%2,%3};"
        : "+f"(c[0]), "+f"(c[1]), "+f"(c[2]), "+f"(c[3])
        : "r"(a[0]), "r"(a[1]), "r"(a[2]), "r"(a[3]), "r"(b0), "r"(b1));
}

// layer 0: A = Aext (fp32, split on the fly), K=128, out = g_h/g_als/g_ald.
// layer 1: A = g_x1 (device-side select), K=256, out = g_h2/g_als2/g_ald2.
__global__ void __launch_bounds__(256)
gemm_mma_kernel(int layer, int M, const float* __restrict__ Aext,
                const float* __restrict__ asrc, const float* __restrict__ adst) {
    const int K = layer ? 256 : 128;
    const float* __restrict__ A = layer ? g_x1 : Aext;
    const __nv_bfloat16* __restrict__ bhi = layer ? g_b2hi : g_b1hi;
    const __nv_bfloat16* __restrict__ blo = layer ? g_b2lo : g_b1lo;
    __half* __restrict__ Cout = layer ? g_h2 : g_h;
    float* __restrict__ alsO = layer ? g_als2 : g_als;
    float* __restrict__ aldO = layer ? g_ald2 : g_ald;

    __shared__ __nv_bfloat16 sAhi[128][40];
    __shared__ __nv_bfloat16 sAlo[128][40];
    __shared__ __nv_bfloat16 sBhi[128][40];
    __shared__ __nv_bfloat16 sBlo[128][40];

    const int tid = threadIdx.x, lane = tid & 31, wid = tid >> 5;
    const int wm = wid >> 2, wn = wid & 3;
    const int row0 = blockIdx.x * 128;
    const int n0 = blockIdx.y * 128;
    const int qid = lane >> 2, qlane = lane & 3;

    float c[4][4][4];
    #pragma unroll
    for (int i = 0; i < 4; i++)
        #pragma unroll
        for (int j = 0; j < 4; j++)
            #pragma unroll
            for (int k = 0; k < 4; k++) c[i][j][k] = 0.f;

    const int nkb = K >> 5;
    for (int kb = 0; kb < nkb; kb++) {
        #pragma unroll
        for (int i = 0; i < 4; i++) {
            int idx = tid + 256 * i;         // 0..1023
            int r = idx >> 3, kq = idx & 7;
            int gr = row0 + r;
            float4 v = make_float4(0.f, 0.f, 0.f, 0.f);
            if (gr < M) v = *(const float4*)&A[(size_t)gr * K + kb * 32 + kq * 4];
            __nv_bfloat162 h01 = __floats2bfloat162_rn(v.x, v.y);
            __nv_bfloat162 h23 = __floats2bfloat162_rn(v.z, v.w);
            __nv_bfloat162 l01 = __floats2bfloat162_rn(v.x - __low2float(h01),
                                                       v.y - __high2float(h01));
            __nv_bfloat162 l23 = __floats2bfloat162_rn(v.z - __low2float(h23),
                                                       v.w - __high2float(h23));
            *(uint2*)&sAhi[r][kq * 4] = make_uint2(*(uint32_t*)&h01, *(uint32_t*)&h23);
            *(uint2*)&sAlo[r][kq * 4] = make_uint2(*(uint32_t*)&l01, *(uint32_t*)&l23);
            size_t gb = (size_t)(n0 + r) * K + kb * 32 + kq * 4;
            *(uint2*)&sBhi[r][kq * 4] = *(const uint2*)&bhi[gb];
            *(uint2*)&sBlo[r][kq * 4] = *(const uint2*)&blo[gb];
        }
        __syncthreads();

        #pragma unroll
        for (int ks = 0; ks < 2; ks++) {
            const int k0 = ks * 16;
            uint32_t ah[4][4], al[4][4];
            #pragma unroll
            for (int mi = 0; mi < 4; mi++) {
                int r = wm * 64 + mi * 16 + qid;
                int cw = k0 + qlane * 2;
                ah[mi][0] = *(const uint32_t*)&sAhi[r][cw];
                ah[mi][1] = *(const uint32_t*)&sAhi[r + 8][cw];
                ah[mi][2] = *(const uint32_t*)&sAhi[r][cw + 8];
                ah[mi][3] = *(const uint32_t*)&sAhi[r + 8][cw + 8];
                al[mi][0] = *(const uint32_t*)&sAlo[r][cw];
                al[mi][1] = *(const uint32_t*)&sAlo[r + 8][cw];
                al[mi][2] = *(const uint32_t*)&sAlo[r][cw + 8];
                al[mi][3] = *(const uint32_t*)&sAlo[r + 8][cw + 8];
            }
            #pragma unroll
            for (int ni = 0; ni < 4; ni++) {
                int n = wn * 32 + ni * 8 + qid;
                int kw = k0 + qlane * 2;
                uint32_t bh0 = *(const uint32_t*)&sBhi[n][kw];
                uint32_t bh1 = *(const uint32_t*)&sBhi[n][kw + 8];
                uint32_t bl0 = *(const uint32_t*)&sBlo[n][kw];
                uint32_t bl1 = *(const uint32_t*)&sBlo[n][kw + 8];
                #pragma unroll
                for (int mi = 0; mi < 4; mi++) {
                    mma_bf16(c[mi][ni], ah[mi], bh0, bh1);
                    mma_bf16(c[mi][ni], ah[mi], bl0, bl1);
                    mma_bf16(c[mi][ni], al[mi], bh0, bh1);
                }
            }
        }
        __syncthreads();
    }

    // ---- fused attention logits (fp32, from accumulators) ----
    const int head = (n0 >> 5) + wn;
    float as_v[4][2], ad_v[4][2];
    #pragma unroll
    for (int ni = 0; ni < 4; ni++)
        #pragma unroll
        for (int j = 0; j < 2; j++) {
            int col = head * 32 + ni * 8 + qlane * 2 + j;
            as_v[ni][j] = asrc[col];
            ad_v[ni][j] = adst[col];
        }
    #pragma unroll
    for (int mi = 0; mi < 4; mi++) {
        #pragma unroll
        for (int h = 0; h < 2; h++) {
            float ps = 0.f, pd = 0.f;
            #pragma unroll
            for (int ni = 0; ni < 4; ni++)
                #pragma unroll
                for (int j = 0; j < 2; j++) {
                    float v = c[mi][ni][h * 2 + j];
                    ps = fmaf(v, as_v[ni][j], ps);
                    pd = fmaf(v, ad_v[ni][j], pd);
                }
            ps += __shfl_xor_sync(0xffffffffu, ps, 1);
            ps += __shfl_xor_sync(0xffffffffu, ps, 2);
            pd += __shfl_xor_sync(0xffffffffu, pd, 1);
            pd += __shfl_xor_sync(0xffffffffu, pd, 2);
            int row = row0 + wm * 64 + mi * 16 + h * 8 + qid;
            if (qlane == 0 && row < M) {
                alsO[row * NHEAD + head] = ps;
                aldO[row * NHEAD + head] = pd;
            }
        }
    }
    // ---- store C as fp16 ----
    #pragma unroll
    for (int mi = 0; mi < 4; mi++) {
        int r = row0 + wm * 64 + mi * 16 + qid;
        #pragma unroll
        for (int ni = 0; ni < 4; ni++) {
            int cg = n0 + wn * 32 + ni * 8 + qlane * 2;
            if (r < M)
                *(__half2*)&Cout[(size_t)r * HID + cg] = __floats2half2_rn(c[mi][ni][0], c[mi][ni][1]);
            if (r + 8 < M)
                *(__half2*)&Cout[(size_t)(r + 8) * HID + cg] = __floats2half2_rn(c[mi][ni][2], c[mi][ni][3]);
        }
    }
}

// ================= segmented softmax + aggregation + bias + ELU =================
// Persistent CTAs stride over nodes. Double-buffered weight smem -> 1 barrier/tile.
// layer 0: read g_h/g_als/g_ald, write g_x1. layer 1: read g_h2/g_als2/g_ald2, write outp.
__global__ void __launch_bounds__(256)
gat_agg_kernel(const float* __restrict__ bias, float* __restrict__ outp, int layer) {
    const __half* __restrict__ hbuf = layer ? g_h2 : g_h;
    const float* __restrict__ alsI = layer ? g_als2 : g_als;
    const float* __restrict__ aldI = layer ? g_ald2 : g_ald;
    float* __restrict__ obase = layer ? outp : g_x1;

    const int tid = threadIdx.x, lane = tid & 31, warp = tid >> 5;
    const int cg = tid & 63;          // 64 channel-groups of 4 channels
    const int sub = tid >> 6;         // 4 concurrent edge sub-streams
    const int headc = cg >> 3;        // head owning these channels

    __shared__ float sh_s[8];
    __shared__ float sh_w[2][8][32];
    __shared__ int   sh_src[2][32];
    __shared__ float4 sh_red[256];

    // hoisted bias (used only by tid < 64 in the tail)
    float4 bvec = make_float4(0.f, 0.f, 0.f, 0.f);
    if (tid < 64) bvec = *(const float4*)&bias[tid * 4];

    for (int v = blockIdx.x; v < NNODES; v += gridDim.x) {
        const int start = g_rowptr[v], end = g_rowptr[v + 1];
        const float aldv = aldI[v * NHEAD + warp];

        float ssum = 0.f;
        float4 acc = make_float4(0.f, 0.f, 0.f, 0.f);
        int p = 0;

        for (int t = start; t < end; t += 32, p ^= 1) {
            int cnt = min(32, end - t);
            if (lane < cnt) {
                int s = g_srcs[t + lane];
                if (warp == 0) sh_src[p][lane] = s;
                float e = alsI[s * NHEAD + warp] + aldv;
                e = (e > 0.f) ? e : 0.2f * e;
                float w = __expf(e);
                sh_w[p][warp][lane] = w;
                ssum += w;
            }
            __syncthreads();
            for (int j = sub; j < cnt; j += 4) {
                int s = sh_src[p][j];
                float w = sh_w[p][headc][j];
                uint2 raw = *reinterpret_cast<const uint2*>(&hbuf[(size_t)s * HID + cg * 4]);
                float2 f01 = __half22float2(*reinterpret_cast<__half2*>(&raw.x));
                float2 f23 = __half22float2(*reinterpret_cast<__half2*>(&raw.y));
                acc.x = fmaf(w, f01.x, acc.x);
                acc.y = fmaf(w, f01.y, acc.y);
                acc.z = fmaf(w, f23.x, acc.z);
                acc.w = fmaf(w, f23.y, acc.w);
            }
            // no trailing barrier: next tile writes the other parity
        }

        #pragma unroll
        for (int o = 16; o; o >>= 1) ssum += __shfl_xor_sync(0xffffffffu, ssum, o);
        if (lane == 0) sh_s[warp] = ssum;

        sh_red[tid] = acc;
        __syncthreads();

        if (tid < 64) {
            float4 a0 = sh_red[tid];
            float4 a1 = sh_red[tid + 64];
            float4 a2 = sh_red[tid + 128];
            float4 a3 = sh_red[tid + 192];
            float r0 = a0.x + a1.x + a2.x + a3.x;
            float r1 = a0.y + a1.y + a2.y + a3.y;
            float r2 = a0.z + a1.z + a2.z + a3.z;
            float r3 = a0.w + a1.w + a2.w + a3.w;
            float inv = 1.f / (sh_s[tid >> 3] + 1e-16f);
            float o0 = r0 * inv + bvec.x;
            float o1 = r1 * inv + bvec.y;
            float o2 = r2 * inv + bvec.z;
            float o3 = r3 * inv + bvec.w;
            o0 = (o0 > 0.f) ? o0 : (__expf(o0) - 1.f);
            o1 = (o1 > 0.f) ? o1 : (__expf(o1) - 1.f);
            o2 = (o2 > 0.f) ? o2 : (__expf(o2) - 1.f);
            o3 = (o3 > 0.f) ? o3 : (__expf(o3) - 1.f);
            float* dstp = obase + (size_t)v * HID + tid * 4;
            dstp[0] = o0; dstp[1] = o1; dstp[2] = o2; dstp[3] = o3;
        }
        __syncthreads();   // protect smem reuse for the next node
    }
}

// ================= driver (round-8 schedule) =================
extern "C" void kernel_launch(void* const* d_in, const int* in_sizes, int n_in,
                              void* d_out, int out_size) {
    const float* x    = (const float*)d_in[0];
    const int*   ei   = (const int*)d_in[1];
    const float* W1   = (const float*)d_in[2];
    const float* a1s  = (const float*)d_in[3];
    const float* a1d  = (const float*)d_in[4];
    const float* b1   = (const float*)d_in[5];
    const float* W2   = (const float*)d_in[6];
    const float* a2s  = (const float*)d_in[7];
    const float* a2d  = (const float*)d_in[8];
    const float* b2   = (const float*)d_in[9];
    float* out = (float*)d_out;

    int etot = in_sizes[1] / 2;
    const int* src = ei;
    const int* dst = ei + etot;
    int eb4 = (etot / 4 + 255) / 256 + 1;

    static cudaStream_t s_side = nullptr;
    static cudaEvent_t ev_fork = nullptr, ev_join = nullptr;
    if (!s_side) {
        cudaStreamCreateWithFlags(&s_side, cudaStreamNonBlocking);
        cudaEventCreateWithFlags(&ev_fork, cudaEventDisableTiming);
        cudaEventCreateWithFlags(&ev_join, cudaEventDisableTiming);
    }

    // ---- main: weight split (needed by gemm1) ----
    convW_kernel<<<(128 * HID + HID * HID + 255) / 256, 256>>>(W1, W2);

    // ---- fork: CSR build on side stream, concurrent with gemm1 ----
    cudaEventRecord(ev_fork, 0);
    cudaStreamWaitEvent(s_side, ev_fork, 0);
    zero_counts_kernel<<<(NNODES + 256) / 256, 256, 0, s_side>>>();
    hist_kernel<<<eb4, 256, 0, s_side>>>(dst, etot);
    scan_local_kernel<<<SCAN_NB, 256, 0, s_side>>>();
    scan_bsums_kernel<<<1, 256, 0, s_side>>>();
    scan_add_kernel<<<SCAN_NB, 256, 0, s_side>>>();
    scatter_kernel<<<eb4, 256, 0, s_side>>>(src, dst, etot);
    cudaEventRecord(ev_join, s_side);

    // ---- main: layer-1 GEMM (independent of CSR) ----
    dim3 ggrid((NNODES + 127) / 128, 2);
    gemm_mma_kernel<<<ggrid, 256>>>(0, NNODES, x, a1s, a1d);

    // ---- join, then the strictly-ordered tail ----
    cudaStreamWaitEvent(0, ev_join, 0);
    gat_agg_kernel<<<AGG_GRID, 256>>>(b1, nullptr, 0);
    gemm_mma_kernel<<<ggrid, 256>>>(1, NNODES, nullptr, a2s, a2d);
    gat_agg_kernel<<<AGG_GRID, 256>>>(b2, out, 1);
}

// round 16
// speedup vs baseline: 1.4125x; 1.1512x over previous
#include <cuda_runtime.h>
#include <cuda_bf16.h>
#include <cuda_fp16.h>
#include <cstdint>

#define NNODES   50000
#define ETOT_MAX 900000
#define HID      256
#define NHEAD    8
#define SCAN_NB  196          // 196*256 = 50176 >= NNODES
#define AGG_GRID 1184         // 148 SMs * 8 resident CTAs

// ================= scratch (static device globals) =================
__device__ int   g_rowptr[NNODES + 1];
__device__ int   g_cursor[NNODES];
__device__ int   g_scantmp[NNODES];
__device__ int   g_bsum[256];
__device__ int   g_srcs[ETOT_MAX];
__device__ __align__(16) __half g_h[NNODES * HID];   // layer-1 features (fp16 for gather BW)
__device__ __align__(16) __half g_h2[NNODES * HID];  // layer-2 features
__device__ __align__(16) float g_x1[NNODES * HID];   // layer-1 aggregated output (fp32)
__device__ __align__(16) float g_als[NNODES * NHEAD];
__device__ __align__(16) float g_ald[NNODES * NHEAD];
__device__ __align__(16) float g_als2[NNODES * NHEAD];
__device__ __align__(16) float g_ald2[NNODES * NHEAD];
// tf32-rounded weights, stored [n][k]
__device__ __align__(16) float g_b1t[HID * 128];
__device__ __align__(16) float g_b2t[HID * HID];

__device__ __forceinline__ float to_tf32(float x) {
    float r;
    asm("cvt.rna.tf32.f32 %0, %1;" : "=f"(r) : "f"(x));
    return r;
}

// ================= CSR build =================
__global__ void zero_counts_kernel() {
    int i = blockIdx.x * blockDim.x + threadIdx.x;
    if (i <= NNODES) g_rowptr[i] = 0;
}

__global__ void hist_kernel(const int* __restrict__ dst, int etot) {
    int i = blockIdx.x * blockDim.x + threadIdx.x;
    int n4 = etot >> 2;
    if (i < n4) {
        int4 d = ((const int4*)dst)[i];
        atomicAdd(&g_rowptr[d.x], 1);
        atomicAdd(&g_rowptr[d.y], 1);
        atomicAdd(&g_rowptr[d.z], 1);
        atomicAdd(&g_rowptr[d.w], 1);
    }
    int rem = etot - n4 * 4;
    if (i < rem) atomicAdd(&g_rowptr[dst[n4 * 4 + i]], 1);
}

__global__ void scan_local_kernel() {
    int t = threadIdx.x, i = blockIdx.x * 256 + t;
    int lane = t & 31, wid = t >> 5;
    int val = (i < NNODES) ? g_rowptr[i] : 0;
    int x = val;
    #pragma unroll
    for (int o = 1; o < 32; o <<= 1) {
        int y = __shfl_up_sync(0xffffffffu, x, o);
        if (lane >= o) x += y;
    }
    __shared__ int wsum[8];
    if (lane == 31) wsum[wid] = x;
    __syncthreads();
    if (t < 8) {
        int s = wsum[t];
        #pragma unroll
        for (int o = 1; o < 8; o <<= 1) {
            int y = __shfl_up_sync(0xffu, s, o);
            if (t >= o) s += y;
        }
        wsum[t] = s;
    }
    __syncthreads();
    int incl = x + (wid ? wsum[wid - 1] : 0);
    if (i < NNODES) g_scantmp[i] = incl - val;
    if (t == 255) g_bsum[blockIdx.x] = incl;
}

__global__ void scan_bsums_kernel() {
    int t = threadIdx.x;
    int lane = t & 31, wid = t >> 5;
    int val = (t < SCAN_NB) ? g_bsum[t] : 0;
    int x = val;
    #pragma unroll
    for (int o = 1; o < 32; o <<= 1) {
        int y = __shfl_up_sync(0xffffffffu, x, o);
        if (lane >= o) x += y;
    }
    __shared__ int wsum[8];
    if (lane == 31) wsum[wid] = x;
    __syncthreads();
    if (t < 8) {
        int s = wsum[t];
        #pragma unroll
        for (int o = 1; o < 8; o <<= 1) {
            int y = __shfl_up_sync(0xffu, s, o);
            if (t >= o) s += y;
        }
        wsum[t] = s;
    }
    __syncthreads();
    int incl = x + (wid ? wsum[wid - 1] : 0);
    if (t < SCAN_NB) g_bsum[t] = incl - val;
    if (t == 255) g_rowptr[NNODES] = incl;
}

__global__ void scan_add_kernel() {
    int i = blockIdx.x * 256 + threadIdx.x;
    if (i < NNODES) {
        int e = g_scantmp[i] + g_bsum[blockIdx.x];
        g_rowptr[i] = e;
        g_cursor[i] = e;
    }
}

__global__ void scatter_kernel(const int* __restrict__ src,
                               const int* __restrict__ dst, int etot) {
    int i = blockIdx.x * blockDim.x + threadIdx.x;
    int n4 = etot >> 2;
    if (i < n4) {
        int4 s = ((const int4*)src)[i];
        int4 d = ((const int4*)dst)[i];
        g_srcs[atomicAdd(&g_cursor[d.x], 1)] = s.x;
        g_srcs[atomicAdd(&g_cursor[d.y], 1)] = s.y;
        g_srcs[atomicAdd(&g_cursor[d.z], 1)] = s.z;
        g_srcs[atomicAdd(&g_cursor[d.w], 1)] = s.w;
    }
    int rem = etot - n4 * 4;
    if (i < rem) {
        int j = n4 * 4 + i;
        g_srcs[atomicAdd(&g_cursor[dst[j]], 1)] = src[j];
    }
}

// ================= weight fp32 -> tf32 (transposed to [n][k]) =================
__global__ void convW_kernel(const float* __restrict__ W1, const float* __restrict__ W2) {
    int i = blockIdx.x * blockDim.x + threadIdx.x;
    const int n1 = 128 * HID;
    if (i < n1) {                       // W1 [128][256]
        int k = i / HID, n = i - k * HID;
        g_b1t[n * 128 + k] = to_tf32(W1[i]);
    } else if (i < n1 + HID * HID) {    // W2 [256][256]
        int j = i - n1;
        int k = j / HID, n = j - k * HID;
        g_b2t[n * HID + k] = to_tf32(W2[j]);
    }
}

// ================= tf32 mma.sync GEMM with fused attention logits =================
__device__ __forceinline__ void mma_tf32(float* c, const uint32_t* a, uint32_t b0, uint32_t b1) {
    asm volatile("mma.sync.aligned.m16n8k8.row.col.f32.tf32.tf32.f32 "
        "{%0,%1,%2,%3}, {%4,%5,%6,%7}, {%8,%9}, {%0,%1,%2,%3};"
        : "+f"(c[0]), "+f"(c[1]), "+f"(c[2]), "+f"(c[3])
        : "r"(a[0]), "r"(a[1]), "r"(a[2]), "r"(a[3]), "r"(b0), "r"(b1));
}

// layer 0: A = Aext (fp32 -> tf32 on the fly), K=128, out = g_h/g_als/g_ald.
// layer 1: A = g_x1 (device-side select), K=256, out = g_h2/g_als2/g_ald2.
__global__ void __launch_bounds__(256)
gemm_mma_kernel(int layer, int M, const float* __restrict__ Aext,
                const float* __restrict__ asrc, const float* __restrict__ adst) {
    const int K = layer ? 256 : 128;
    const float* __restrict__ A = layer ? g_x1 : Aext;
    const float* __restrict__ Bt = layer ? g_b2t : g_b1t;
    __half* __restrict__ Cout = layer ? g_h2 : g_h;
    float* __restrict__ alsO = layer ? g_als2 : g_als;
    float* __restrict__ aldO = layer ? g_ald2 : g_ald;

    // pad 36 words: fragment LDS addr mod 32 = 4*qid + qlane -> conflict-free
    __shared__ uint32_t sA[128][36];
    __shared__ uint32_t sB[128][36];

    const int tid = threadIdx.x, lane = tid & 31, wid = tid >> 5;
    const int wm = wid >> 2, wn = wid & 3;
    const int row0 = blockIdx.x * 128;
    const int n0 = blockIdx.y * 128;
    const int qid = lane >> 2, qlane = lane & 3;

    float c[4][4][4];
    #pragma unroll
    for (int i = 0; i < 4; i++)
        #pragma unroll
        for (int j = 0; j < 4; j++)
            #pragma unroll
            for (int k = 0; k < 4; k++) c[i][j][k] = 0.f;

    const int nkb = K >> 5;
    for (int kb = 0; kb < nkb; kb++) {
        #pragma unroll
        for (int i = 0; i < 4; i++) {
            int idx = tid + 256 * i;         // 0..1023
            int r = idx >> 3, kq = idx & 7;  // row, 4-float quad
            int gr = row0 + r;
            float4 v = make_float4(0.f, 0.f, 0.f, 0.f);
            if (gr < M) v = *(const float4*)&A[(size_t)gr * K + kb * 32 + kq * 4];
            uint4 av;
            av.x = __float_as_uint(to_tf32(v.x));
            av.y = __float_as_uint(to_tf32(v.y));
            av.z = __float_as_uint(to_tf32(v.z));
            av.w = __float_as_uint(to_tf32(v.w));
            *(uint4*)&sA[r][kq * 4] = av;
            // B: already tf32-rounded
            *(uint4*)&sB[r][kq * 4] =
                *(const uint4*)&Bt[(size_t)(n0 + r) * K + kb * 32 + kq * 4];
        }
        __syncthreads();

        #pragma unroll
        for (int ks = 0; ks < 4; ks++) {
            const int k0 = ks * 8;
            uint32_t a[4][4];
            #pragma unroll
            for (int mi = 0; mi < 4; mi++) {
                int m = wm * 64 + mi * 16 + qid;
                a[mi][0] = sA[m][k0 + qlane];
                a[mi][1] = sA[m + 8][k0 + qlane];
                a[mi][2] = sA[m][k0 + qlane + 4];
                a[mi][3] = sA[m + 8][k0 + qlane + 4];
            }
            #pragma unroll
            for (int ni = 0; ni < 4; ni++) {
                int n = wn * 32 + ni * 8 + qid;
                uint32_t b0 = sB[n][k0 + qlane];
                uint32_t b1 = sB[n][k0 + qlane + 4];
                #pragma unroll
                for (int mi = 0; mi < 4; mi++)
                    mma_tf32(c[mi][ni], a[mi], b0, b1);
            }
        }
        __syncthreads();
    }

    // ---- fused attention logits (fp32, from accumulators) ----
    const int head = (n0 >> 5) + wn;
    float as_v[4][2], ad_v[4][2];
    #pragma unroll
    for (int ni = 0; ni < 4; ni++)
        #pragma unroll
        for (int j = 0; j < 2; j++) {
            int col = head * 32 + ni * 8 + qlane * 2 + j;
            as_v[ni][j] = asrc[col];
            ad_v[ni][j] = adst[col];
        }
    #pragma unroll
    for (int mi = 0; mi < 4; mi++) {
        #pragma unroll
        for (int h = 0; h < 2; h++) {
            float ps = 0.f, pd = 0.f;
            #pragma unroll
            for (int ni = 0; ni < 4; ni++)
                #pragma unroll
                for (int j = 0; j < 2; j++) {
                    float v = c[mi][ni][h * 2 + j];
                    ps = fmaf(v, as_v[ni][j], ps);
                    pd = fmaf(v, ad_v[ni][j], pd);
                }
            ps += __shfl_xor_sync(0xffffffffu, ps, 1);
            ps += __shfl_xor_sync(0xffffffffu, ps, 2);
            pd += __shfl_xor_sync(0xffffffffu, pd, 1);
            pd += __shfl_xor_sync(0xffffffffu, pd, 2);
            int row = row0 + wm * 64 + mi * 16 + h * 8 + qid;
            if (qlane == 0 && row < M) {
                alsO[row * NHEAD + head] = ps;
                aldO[row * NHEAD + head] = pd;
            }
        }
    }
    // ---- store C as fp16 ----
    #pragma unroll
    for (int mi = 0; mi < 4; mi++) {
        int r = row0 + wm * 64 + mi * 16 + qid;
        #pragma unroll
        for (int ni = 0; ni < 4; ni++) {
            int cg = n0 + wn * 32 + ni * 8 + qlane * 2;
            if (r < M)
                *(__half2*)&Cout[(size_t)r * HID + cg] = __floats2half2_rn(c[mi][ni][0], c[mi][ni][1]);
            if (r + 8 < M)
                *(__half2*)&Cout[(size_t)(r + 8) * HID + cg] = __floats2half2_rn(c[mi][ni][2], c[mi][ni][3]);
        }
    }
}

// ================= segmented softmax + aggregation + bias + ELU =================
// Persistent CTAs stride over nodes. Double-buffered weight smem -> 1 barrier/tile.
__global__ void __launch_bounds__(256)
gat_agg_kernel(const float* __restrict__ bias, float* __restrict__ outp, int layer) {
    const __half* __restrict__ hbuf = layer ? g_h2 : g_h;
    const float* __restrict__ alsI = layer ? g_als2 : g_als;
    const float* __restrict__ aldI = layer ? g_ald2 : g_ald;
    float* __restrict__ obase = layer ? outp : g_x1;

    const int tid = threadIdx.x, lane = tid & 31, warp = tid >> 5;
    const int cg = tid & 63;
    const int sub = tid >> 6;
    const int headc = cg >> 3;

    __shared__ float sh_s[8];
    __shared__ float sh_w[2][8][32];
    __shared__ int   sh_src[2][32];
    __shared__ float4 sh_red[256];

    float4 bvec = make_float4(0.f, 0.f, 0.f, 0.f);
    if (tid < 64) bvec = *(const float4*)&bias[tid * 4];

    for (int v = blockIdx.x; v < NNODES; v += gridDim.x) {
        const int start = g_rowptr[v], end = g_rowptr[v + 1];
        const float aldv = aldI[v * NHEAD + warp];

        float ssum = 0.f;
        float4 acc = make_float4(0.f, 0.f, 0.f, 0.f);
        int p = 0;

        for (int t = start; t < end; t += 32, p ^= 1) {
            int cnt = min(32, end - t);
            if (lane < cnt) {
                int s = g_srcs[t + lane];
                if (warp == 0) sh_src[p][lane] = s;
                float e = alsI[s * NHEAD + warp] + aldv;
                e = (e > 0.f) ? e : 0.2f * e;
                float w = __expf(e);
                sh_w[p][warp][lane] = w;
                ssum += w;
            }
            __syncthreads();
            for (int j = sub; j < cnt; j += 4) {
                int s = sh_src[p][j];
                float w = sh_w[p][headc][j];
                uint2 raw = *reinterpret_cast<const uint2*>(&hbuf[(size_t)s * HID + cg * 4]);
                float2 f01 = __half22float2(*reinterpret_cast<__half2*>(&raw.x));
                float2 f23 = __half22float2(*reinterpret_cast<__half2*>(&raw.y));
                acc.x = fmaf(w, f01.x, acc.x);
                acc.y = fmaf(w, f01.y, acc.y);
                acc.z = fmaf(w, f23.x, acc.z);
                acc.w = fmaf(w, f23.y, acc.w);
            }
        }

        #pragma unroll
        for (int o = 16; o; o >>= 1) ssum += __shfl_xor_sync(0xffffffffu, ssum, o);
        if (lane == 0) sh_s[warp] = ssum;

        sh_red[tid] = acc;
        __syncthreads();

        if (tid < 64) {
            float4 a0 = sh_red[tid];
            float4 a1 = sh_red[tid + 64];
            float4 a2 = sh_red[tid + 128];
            float4 a3 = sh_red[tid + 192];
            float r0 = a0.x + a1.x + a2.x + a3.x;
            float r1 = a0.y + a1.y + a2.y + a3.y;
            float r2 = a0.z + a1.z + a2.z + a3.z;
            float r3 = a0.w + a1.w + a2.w + a3.w;
            float inv = 1.f / (sh_s[tid >> 3] + 1e-16f);
            float o0 = r0 * inv + bvec.x;
            float o1 = r1 * inv + bvec.y;
            float o2 = r2 * inv + bvec.z;
            float o3 = r3 * inv + bvec.w;
            o0 = (o0 > 0.f) ? o0 : (__expf(o0) - 1.f);
            o1 = (o1 > 0.f) ? o1 : (__expf(o1) - 1.f);
            o2 = (o2 > 0.f) ? o2 : (__expf(o2) - 1.f);
            o3 = (o3 > 0.f) ? o3 : (__expf(o3) - 1.f);
            float* dstp = obase + (size_t)v * HID + tid * 4;
            dstp[0] = o0; dstp[1] = o1; dstp[2] = o2; dstp[3] = o3;
        }
        __syncthreads();
    }
}

// ================= driver (round-8 schedule) =================
extern "C" void kernel_launch(void* const* d_in, const int* in_sizes, int n_in,
                              void* d_out, int out_size) {
    const float* x    = (const float*)d_in[0];
    const int*   ei   = (const int*)d_in[1];
    const float* W1   = (const float*)d_in[2];
    const float* a1s  = (const float*)d_in[3];
    const float* a1d  = (const float*)d_in[4];
    const float* b1   = (const float*)d_in[5];
    const float* W2   = (const float*)d_in[6];
    const float* a2s  = (const float*)d_in[7];
    const float* a2d  = (const float*)d_in[8];
    const float* b2   = (const float*)d_in[9];
    float* out = (float*)d_out;

    int etot = in_sizes[1] / 2;
    const int* src = ei;
    const int* dst = ei + etot;
    int eb4 = (etot / 4 + 255) / 256 + 1;

    static cudaStream_t s_side = nullptr;
    static cudaEvent_t ev_fork = nullptr, ev_join = nullptr;
    if (!s_side) {
        cudaStreamCreateWithFlags(&s_side, cudaStreamNonBlocking);
        cudaEventCreateWithFlags(&ev_fork, cudaEventDisableTiming);
        cudaEventCreateWithFlags(&ev_join, cudaEventDisableTiming);
    }

    // ---- main: weight tf32 conversion (needed by gemm1) ----
    convW_kernel<<<(128 * HID + HID * HID + 255) / 256, 256>>>(W1, W2);

    // ---- fork: CSR build on side stream, concurrent with gemm1 ----
    cudaEventRecord(ev_fork, 0);
    cudaStreamWaitEvent(s_side, ev_fork, 0);
    zero_counts_kernel<<<(NNODES + 256) / 256, 256, 0, s_side>>>();
    hist_kernel<<<eb4, 256, 0, s_side>>>(dst, etot);
    scan_local_kernel<<<SCAN_NB, 256, 0, s_side>>>();
    scan_bsums_kernel<<<1, 256, 0, s_side>>>();
    scan_add_kernel<<<SCAN_NB, 256, 0, s_side>>>();
    scatter_kernel<<<eb4, 256, 0, s_side>>>(src, dst, etot);
    cudaEventRecord(ev_join, s_side);

    // ---- main: layer-1 GEMM (independent of CSR) ----
    dim3 ggrid((NNODES + 127) / 128, 2);
    gemm_mma_kernel<<<ggrid, 256>>>(0, NNODES, x, a1s, a1d);

    // ---- join, then the strictly-ordered tail ----
    cudaStreamWaitEvent(0, ev_join, 0);
    gat_agg_kernel<<<AGG_GRID, 256>>>(b1, nullptr, 0);
    gemm_mma_kernel<<<ggrid, 256>>>(1, NNODES, nullptr, a2s, a2d);
    gat_agg_kernel<<<AGG_GRID, 256>>>(b2, out, 1);
}

// round 17
// speedup vs baseline: 1.4948x; 1.0583x over previous
#include <cuda_runtime.h>
#include <cuda_bf16.h>
#include <cuda_fp16.h>
#include <cstdint>

#define NNODES   50000
#define ETOT_MAX 900000
#define HID      256
#define NHEAD    8
#define SCAN_NB  196          // 196*256 = 50176 >= NNODES
#define AGG_GRID 1184         // 148 SMs * 8 resident CTAs

// ================= scratch (static device globals) =================
__device__ int   g_rowptr[NNODES + 1];
__device__ int   g_cursor[NNODES];
__device__ int   g_scantmp[NNODES];
__device__ int   g_bsum[256];
__device__ int   g_srcs[ETOT_MAX];
__device__ __align__(16) __half g_h[NNODES * HID];   // layer-1 features (fp16 for gather BW)
__device__ __align__(16) __half g_h2[NNODES * HID];  // layer-2 features
__device__ __align__(16) float g_x1[NNODES * HID];   // layer-1 aggregated output (fp32)
__device__ __align__(16) float g_als[NNODES * NHEAD];
__device__ __align__(16) float g_ald[NNODES * NHEAD];
__device__ __align__(16) float g_als2[NNODES * NHEAD];
__device__ __align__(16) float g_ald2[NNODES * NHEAD];
// tf32-rounded weights, stored [n][k]
__device__ __align__(16) float g_b1t[HID * 128];
__device__ __align__(16) float g_b2t[HID * HID];

__device__ __forceinline__ float to_tf32(float x) {
    float r;
    asm("cvt.rna.tf32.f32 %0, %1;" : "=f"(r) : "f"(x));
    return r;
}

// ================= CSR build =================
__global__ void zero_counts_kernel() {
    int i = blockIdx.x * blockDim.x + threadIdx.x;
    if (i <= NNODES) g_rowptr[i] = 0;
}

__global__ void hist_kernel(const int* __restrict__ dst, int etot) {
    int i = blockIdx.x * blockDim.x + threadIdx.x;
    int n4 = etot >> 2;
    if (i < n4) {
        int4 d = ((const int4*)dst)[i];
        atomicAdd(&g_rowptr[d.x], 1);
        atomicAdd(&g_rowptr[d.y], 1);
        atomicAdd(&g_rowptr[d.z], 1);
        atomicAdd(&g_rowptr[d.w], 1);
    }
    int rem = etot - n4 * 4;
    if (i < rem) atomicAdd(&g_rowptr[dst[n4 * 4 + i]], 1);
}

__global__ void scan_local_kernel() {
    int t = threadIdx.x, i = blockIdx.x * 256 + t;
    int lane = t & 31, wid = t >> 5;
    int val = (i < NNODES) ? g_rowptr[i] : 0;
    int x = val;
    #pragma unroll
    for (int o = 1; o < 32; o <<= 1) {
        int y = __shfl_up_sync(0xffffffffu, x, o);
        if (lane >= o) x += y;
    }
    __shared__ int wsum[8];
    if (lane == 31) wsum[wid] = x;
    __syncthreads();
    if (t < 8) {
        int s = wsum[t];
        #pragma unroll
        for (int o = 1; o < 8; o <<= 1) {
            int y = __shfl_up_sync(0xffu, s, o);
            if (t >= o) s += y;
        }
        wsum[t] = s;
    }
    __syncthreads();
    int incl = x + (wid ? wsum[wid - 1] : 0);
    if (i < NNODES) g_scantmp[i] = incl - val;
    if (t == 255) g_bsum[blockIdx.x] = incl;
}

__global__ void scan_bsums_kernel() {
    int t = threadIdx.x;
    int lane = t & 31, wid = t >> 5;
    int val = (t < SCAN_NB) ? g_bsum[t] : 0;
    int x = val;
    #pragma unroll
    for (int o = 1; o < 32; o <<= 1) {
        int y = __shfl_up_sync(0xffffffffu, x, o);
        if (lane >= o) x += y;
    }
    __shared__ int wsum[8];
    if (lane == 31) wsum[wid] = x;
    __syncthreads();
    if (t < 8) {
        int s = wsum[t];
        #pragma unroll
        for (int o = 1; o < 8; o <<= 1) {
            int y = __shfl_up_sync(0xffu, s, o);
            if (t >= o) s += y;
        }
        wsum[t] = s;
    }
    __syncthreads();
    int incl = x + (wid ? wsum[wid - 1] : 0);
    if (t < SCAN_NB) g_bsum[t] = incl - val;
    if (t == 255) g_rowptr[NNODES] = incl;
}

__global__ void scan_add_kernel() {
    int i = blockIdx.x * 256 + threadIdx.x;
    if (i < NNODES) {
        int e = g_scantmp[i] + g_bsum[blockIdx.x];
        g_rowptr[i] = e;
        g_cursor[i] = e;
    }
}

__global__ void scatter_kernel(const int* __restrict__ src,
                               const int* __restrict__ dst, int etot) {
    int i = blockIdx.x * blockDim.x + threadIdx.x;
    int n4 = etot >> 2;
    if (i < n4) {
        int4 s = ((const int4*)src)[i];
        int4 d = ((const int4*)dst)[i];
        g_srcs[atomicAdd(&g_cursor[d.x], 1)] = s.x;
        g_srcs[atomicAdd(&g_cursor[d.y], 1)] = s.y;
        g_srcs[atomicAdd(&g_cursor[d.z], 1)] = s.z;
        g_srcs[atomicAdd(&g_cursor[d.w], 1)] = s.w;
    }
    int rem = etot - n4 * 4;
    if (i < rem) {
        int j = n4 * 4 + i;
        g_srcs[atomicAdd(&g_cursor[dst[j]], 1)] = src[j];
    }
}

// ================= weight fp32 -> tf32 (transposed to [n][k]) =================
__global__ void convW_kernel(const float* __restrict__ W1, const float* __restrict__ W2) {
    int i = blockIdx.x * blockDim.x + threadIdx.x;
    const int n1 = 128 * HID;
    if (i < n1) {                       // W1 [128][256]
        int k = i / HID, n = i - k * HID;
        g_b1t[n * 128 + k] = to_tf32(W1[i]);
    } else if (i < n1 + HID * HID) {    // W2 [256][256]
        int j = i - n1;
        int k = j / HID, n = j - k * HID;
        g_b2t[n * HID + k] = to_tf32(W2[j]);
    }
}

// ================= tf32 mma.sync GEMM with fused attention logits =================
__device__ __forceinline__ void mma_tf32(float* c, const uint32_t* a, uint32_t b0, uint32_t b1) {
    asm volatile("mma.sync.aligned.m16n8k8.row.col.f32.tf32.tf32.f32 "
        "{%0,%1,%2,%3}, {%4,%5,%6,%7}, {%8,%9}, {%0,%1,%2,%3};"
        : "+f"(c[0]), "+f"(c[1]), "+f"(c[2]), "+f"(c[3])
        : "r"(a[0]), "r"(a[1]), "r"(a[2]), "r"(a[3]), "r"(b0), "r"(b1));
}

// layer 0: A = Aext (fp32 -> tf32 on the fly), K=128, out = g_h/g_als/g_ald.
// layer 1: A = g_x1 (device-side select), K=256, out = g_h2/g_als2/g_ald2.
__global__ void __launch_bounds__(256)
gemm_mma_kernel(int layer, int M, const float* __restrict__ Aext,
                const float* __restrict__ asrc, const float* __restrict__ adst) {
    const int K = layer ? 256 : 128;
    const float* __restrict__ A = layer ? g_x1 : Aext;
    const float* __restrict__ Bt = layer ? g_b2t : g_b1t;
    __half* __restrict__ Cout = layer ? g_h2 : g_h;
    float* __restrict__ alsO = layer ? g_als2 : g_als;
    float* __restrict__ aldO = layer ? g_ald2 : g_ald;

    __shared__ uint32_t sA[128][36];
    __shared__ uint32_t sB[128][36];

    const int tid = threadIdx.x, lane = tid & 31, wid = tid >> 5;
    const int wm = wid >> 2, wn = wid & 3;
    const int row0 = blockIdx.x * 128;
    const int n0 = blockIdx.y * 128;
    const int qid = lane >> 2, qlane = lane & 3;

    float c[4][4][4];
    #pragma unroll
    for (int i = 0; i < 4; i++)
        #pragma unroll
        for (int j = 0; j < 4; j++)
            #pragma unroll
            for (int k = 0; k < 4; k++) c[i][j][k] = 0.f;

    const int nkb = K >> 5;
    for (int kb = 0; kb < nkb; kb++) {
        #pragma unroll
        for (int i = 0; i < 4; i++) {
            int idx = tid + 256 * i;         // 0..1023
            int r = idx >> 3, kq = idx & 7;
            int gr = row0 + r;
            float4 v = make_float4(0.f, 0.f, 0.f, 0.f);
            if (gr < M) v = *(const float4*)&A[(size_t)gr * K + kb * 32 + kq * 4];
            uint4 av;
            av.x = __float_as_uint(to_tf32(v.x));
            av.y = __float_as_uint(to_tf32(v.y));
            av.z = __float_as_uint(to_tf32(v.z));
            av.w = __float_as_uint(to_tf32(v.w));
            *(uint4*)&sA[r][kq * 4] = av;
            *(uint4*)&sB[r][kq * 4] =
                *(const uint4*)&Bt[(size_t)(n0 + r) * K + kb * 32 + kq * 4];
        }
        __syncthreads();

        #pragma unroll
        for (int ks = 0; ks < 4; ks++) {
            const int k0 = ks * 8;
            uint32_t a[4][4];
            #pragma unroll
            for (int mi = 0; mi < 4; mi++) {
                int m = wm * 64 + mi * 16 + qid;
                a[mi][0] = sA[m][k0 + qlane];
                a[mi][1] = sA[m + 8][k0 + qlane];
                a[mi][2] = sA[m][k0 + qlane + 4];
                a[mi][3] = sA[m + 8][k0 + qlane + 4];
            }
            #pragma unroll
            for (int ni = 0; ni < 4; ni++) {
                int n = wn * 32 + ni * 8 + qid;
                uint32_t b0 = sB[n][k0 + qlane];
                uint32_t b1 = sB[n][k0 + qlane + 4];
                #pragma unroll
                for (int mi = 0; mi < 4; mi++)
                    mma_tf32(c[mi][ni], a[mi], b0, b1);
            }
        }
        __syncthreads();
    }

    // ---- fused attention logits (fp32, from accumulators) ----
    const int head = (n0 >> 5) + wn;
    float as_v[4][2], ad_v[4][2];
    #pragma unroll
    for (int ni = 0; ni < 4; ni++)
        #pragma unroll
        for (int j = 0; j < 2; j++) {
            int col = head * 32 + ni * 8 + qlane * 2 + j;
            as_v[ni][j] = asrc[col];
            ad_v[ni][j] = adst[col];
        }
    #pragma unroll
    for (int mi = 0; mi < 4; mi++) {
        #pragma unroll
        for (int h = 0; h < 2; h++) {
            float ps = 0.f, pd = 0.f;
            #pragma unroll
            for (int ni = 0; ni < 4; ni++)
                #pragma unroll
                for (int j = 0; j < 2; j++) {
                    float v = c[mi][ni][h * 2 + j];
                    ps = fmaf(v, as_v[ni][j], ps);
                    pd = fmaf(v, ad_v[ni][j], pd);
                }
            ps += __shfl_xor_sync(0xffffffffu, ps, 1);
            ps += __shfl_xor_sync(0xffffffffu, ps, 2);
            pd += __shfl_xor_sync(0xffffffffu, pd, 1);
            pd += __shfl_xor_sync(0xffffffffu, pd, 2);
            int row = row0 + wm * 64 + mi * 16 + h * 8 + qid;
            if (qlane == 0 && row < M) {
                alsO[row * NHEAD + head] = ps;
                aldO[row * NHEAD + head] = pd;
            }
        }
    }
    // ---- store C as fp16 ----
    #pragma unroll
    for (int mi = 0; mi < 4; mi++) {
        int r = row0 + wm * 64 + mi * 16 + qid;
        #pragma unroll
        for (int ni = 0; ni < 4; ni++) {
            int cg = n0 + wn * 32 + ni * 8 + qlane * 2;
            if (r < M)
                *(__half2*)&Cout[(size_t)r * HID + cg] = __floats2half2_rn(c[mi][ni][0], c[mi][ni][1]);
            if (r + 8 < M)
                *(__half2*)&Cout[(size_t)(r + 8) * HID + cg] = __floats2half2_rn(c[mi][ni][2], c[mi][ni][3]);
        }
    }
}

// ================= segmented softmax + aggregation + bias + ELU =================
// Persistent CTAs. Weight phase: warp w owns edges 4w..4w+3; lane = edge*8+head,
// so each 8-lane group reads one node's 32B logit row (1 sector, not 8 scattered).
// Gather phase unchanged (proven optimum).
__global__ void __launch_bounds__(256)
gat_agg_kernel(const float* __restrict__ bias, float* __restrict__ outp, int layer) {
    const __half* __restrict__ hbuf = layer ? g_h2 : g_h;
    const float* __restrict__ alsI = layer ? g_als2 : g_als;
    const float* __restrict__ aldI = layer ? g_ald2 : g_ald;
    float* __restrict__ obase = layer ? outp : g_x1;

    const int tid = threadIdx.x, lane = tid & 31, warp = tid >> 5;
    const int cg = tid & 63;          // 64 channel-groups of 4 channels
    const int sub = tid >> 6;         // 4 concurrent edge sub-streams
    const int headc = cg >> 3;        // head owning these channels
    const int ew = (warp << 2) + (lane >> 3);   // edge index owned in weight phase
    const int h8 = lane & 7;                    // head owned in weight phase

    __shared__ float  sh_w[2][32][8];  // [parity][edge][head]
    __shared__ int    sh_src[2][32];
    __shared__ float  sh_ps[8][9];     // per-warp per-head weight sums (padded)
    __shared__ float4 sh_red[256];

    float4 bvec = make_float4(0.f, 0.f, 0.f, 0.f);
    if (tid < 64) bvec = *(const float4*)&bias[tid * 4];

    for (int v = blockIdx.x; v < NNODES; v += gridDim.x) {
        const int start = g_rowptr[v], end = g_rowptr[v + 1];
        const float aldv = aldI[v * NHEAD + h8];

        float ssum = 0.f;                  // per-lane partial for head h8
        float4 acc = make_float4(0.f, 0.f, 0.f, 0.f);
        int p = 0;

        for (int t = start; t < end; t += 32, p ^= 1) {
            int cnt = min(32, end - t);
            if (ew < cnt) {
                int s = g_srcs[t + ew];            // broadcast within 8-lane group
                if (h8 == 0) sh_src[p][ew] = s;
                float e = alsI[s * NHEAD + h8] + aldv;   // one 32B row per group
                e = (e > 0.f) ? e : 0.2f * e;
                float w = __expf(e);
                sh_w[p][ew][h8] = w;
                ssum += w;
            }
            __syncthreads();
            for (int j = sub; j < cnt; j += 4) {
                int s = sh_src[p][j];
                float w = sh_w[p][j][headc];
                uint2 raw = *reinterpret_cast<const uint2*>(&hbuf[(size_t)s * HID + cg * 4]);
                float2 f01 = __half22float2(*reinterpret_cast<__half2*>(&raw.x));
                float2 f23 = __half22float2(*reinterpret_cast<__half2*>(&raw.y));
                acc.x = fmaf(w, f01.x, acc.x);
                acc.y = fmaf(w, f01.y, acc.y);
                acc.z = fmaf(w, f23.x, acc.z);
                acc.w = fmaf(w, f23.y, acc.w);
            }
            // next tile writes the other parity
        }

        // per-head weight sums: lanes sharing h8 differ in bits 3,4
        ssum += __shfl_xor_sync(0xffffffffu, ssum, 8);
        ssum += __shfl_xor_sync(0xffffffffu, ssum, 16);
        if (lane < 8) sh_ps[warp][lane] = ssum;

        sh_red[tid] = acc;
        __syncthreads();

        if (tid < 64) {
            float4 a0 = sh_red[tid];
            float4 a1 = sh_red[tid + 64];
            float4 a2 = sh_red[tid + 128];
            float4 a3 = sh_red[tid + 192];
            float r0 = a0.x + a1.x + a2.x + a3.x;
            float r1 = a0.y + a1.y + a2.y + a3.y;
            float r2 = a0.z + a1.z + a2.z + a3.z;
            float r3 = a0.w + a1.w + a2.w + a3.w;
            int head = tid >> 3;
            float wsum = sh_ps[0][head] + sh_ps[1][head] + sh_ps[2][head] + sh_ps[3][head]
                       + sh_ps[4][head] + sh_ps[5][head] + sh_ps[6][head] + sh_ps[7][head];
            float inv = 1.f / (wsum + 1e-16f);
            float o0 = r0 * inv + bvec.x;
            float o1 = r1 * inv + bvec.y;
            float o2 = r2 * inv + bvec.z;
            float o3 = r3 * inv + bvec.w;
            o0 = (o0 > 0.f) ? o0 : (__expf(o0) - 1.f);
            o1 = (o1 > 0.f) ? o1 : (__expf(o1) - 1.f);
            o2 = (o2 > 0.f) ? o2 : (__expf(o2) - 1.f);
            o3 = (o3 > 0.f) ? o3 : (__expf(o3) - 1.f);
            float* dstp = obase + (size_t)v * HID + tid * 4;
            dstp[0] = o0; dstp[1] = o1; dstp[2] = o2; dstp[3] = o3;
        }
        __syncthreads();   // protect smem reuse for the next node
    }
}

// ================= driver (round-8 schedule) =================
extern "C" void kernel_launch(void* const* d_in, const int* in_sizes, int n_in,
                              void* d_out, int out_size) {
    const float* x    = (const float*)d_in[0];
    const int*   ei   = (const int*)d_in[1];
    const float* W1   = (const float*)d_in[2];
    const float* a1s  = (const float*)d_in[3];
    const float* a1d  = (const float*)d_in[4];
    const float* b1   = (const float*)d_in[5];
    const float* W2   = (const float*)d_in[6];
    const float* a2s  = (const float*)d_in[7];
    const float* a2d  = (const float*)d_in[8];
    const float* b2   = (const float*)d_in[9];
    float* out = (float*)d_out;

    int etot = in_sizes[1] / 2;
    const int* src = ei;
    const int* dst = ei + etot;
    int eb4 = (etot / 4 + 255) / 256 + 1;

    static cudaStream_t s_side = nullptr;
    static cudaEvent_t ev_fork = nullptr, ev_join = nullptr;
    if (!s_side) {
        cudaStreamCreateWithFlags(&s_side, cudaStreamNonBlocking);
        cudaEventCreateWithFlags(&ev_fork, cudaEventDisableTiming);
        cudaEventCreateWithFlags(&ev_join, cudaEventDisableTiming);
    }

    // ---- main: weight tf32 conversion (needed by gemm1) ----
    convW_kernel<<<(128 * HID + HID * HID + 255) / 256, 256>>>(W1, W2);

    // ---- fork: CSR build on side stream, concurrent with gemm1 ----
    cudaEventRecord(ev_fork, 0);
    cudaStreamWaitEvent(s_side, ev_fork, 0);
    zero_counts_kernel<<<(NNODES + 256) / 256, 256, 0, s_side>>>();
    hist_kernel<<<eb4, 256, 0, s_side>>>(dst, etot);
    scan_local_kernel<<<SCAN_NB, 256, 0, s_side>>>();
    scan_bsums_kernel<<<1, 256, 0, s_side>>>();
    scan_add_kernel<<<SCAN_NB, 256, 0, s_side>>>();
    scatter_kernel<<<eb4, 256, 0, s_side>>>(src, dst, etot);
    cudaEventRecord(ev_join, s_side);

    // ---- main: layer-1 GEMM (independent of CSR) ----
    dim3 ggrid((NNODES + 127) / 128, 2);
    gemm_mma_kernel<<<ggrid, 256>>>(0, NNODES, x, a1s, a1d);

    // ---- join, then the strictly-ordered tail ----
    cudaStreamWaitEvent(0, ev_join, 0);
    gat_agg_kernel<<<AGG_GRID, 256>>>(b1, nullptr, 0);
    gemm_mma_kernel<<<ggrid, 256>>>(1, NNODES, nullptr, a2s, a2d);
    gat_agg_kernel<<<AGG_GRID, 256>>>(b2, out, 1);
}